// round 11
// baseline (speedup 1.0000x reference)
#include <cuda_runtime.h>
#include <cuda_bf16.h>
#include <cstdint>

#define BB 8
#define CC_ 128
#define HH 192
#define WW 192
#define HW (HH*WW)
#define CHW (CC_*HW)
#define TOT (BB*CHW)
#define KK 1152            // C*9
#define EPSV 1e-5f
#define NORM_SCALE 0.1816f
#define STAT_N (BB*4*(HH/2)*(WW/2))   // 294912

// padded image geometry (1-px halo + alignment tail)
#define WP 200
#define HP 194
#define PLANE (HP*WP)          // 38800
#define PCHW (CC_*PLANE)
#define PTOT (BB*PCHW)

// ---------------- scratch (device globals; no allocations allowed) ------------
// padded input copies, 3 shifts: A[px]=row[px-1], B[px]=row[px], C[px]=row[px+1]
__device__ __align__(16) __nv_bfloat16 g_pxa_h[PTOT];
__device__ __align__(16) __nv_bfloat16 g_pxa_l[PTOT];
__device__ __align__(16) __nv_bfloat16 g_pxb_h[PTOT];
__device__ __align__(16) __nv_bfloat16 g_pxb_l[PTOT];
__device__ __align__(16) __nv_bfloat16 g_pxc_h[PTOT];
__device__ __align__(16) __nv_bfloat16 g_pxc_l[PTOT];
// padded a3 copies (same 3 shifts)
__device__ __align__(16) __nv_bfloat16 g_paa_h[PTOT];
__device__ __align__(16) __nv_bfloat16 g_paa_l[PTOT];
__device__ __align__(16) __nv_bfloat16 g_pab_h[PTOT];
__device__ __align__(16) __nv_bfloat16 g_pab_l[PTOT];
__device__ __align__(16) __nv_bfloat16 g_pac_h[PTOT];
__device__ __align__(16) __nv_bfloat16 g_pac_l[PTOT];
// parity-packed conv1/conv2 outputs: [b][ch][class(9)][4096]
__device__ __align__(16) __nv_bfloat16 g_a1p_h[TOT];
__device__ __align__(16) __nv_bfloat16 g_a1p_l[TOT];
__device__ __align__(16) __nv_bfloat16 g_a2p_h[TOT];
__device__ __align__(16) __nv_bfloat16 g_a2p_l[TOT];
__device__ float g_av[TOT];
__device__ __align__(16) __nv_bfloat16 g_wh[3*CC_*KK];    // [w][o][knew], knew=(r*3+dx)*128+ic
__device__ __align__(16) __nv_bfloat16 g_wl[3*CC_*KK];
__device__ __align__(16) __nv_bfloat16 g_kh[BB*CC_*KK];   // [b][o][knew]
__device__ __align__(16) __nv_bfloat16 g_kl[BB*CC_*KK];
__device__ float g_attn[BB*CC_*KK];        // [b][o][i*9+class]
__device__ float g_sum[CC_];
__device__ float g_sumsq[CC_];
__device__ float g_mean[CC_];
__device__ float g_inv[CC_];

// ---------------- PTX helpers -------------------------------------------------
__device__ __forceinline__ uint32_t smem_u32(const void* p) {
    uint32_t a;
    asm("{ .reg .u64 t; cvta.to.shared.u64 t, %1; cvt.u32.u64 %0, t; }"
        : "=r"(a) : "l"(p));
    return a;
}
__device__ __forceinline__ void ldsm4(unsigned* r, uint32_t addr) {
    asm volatile("ldmatrix.sync.aligned.m8n8.x4.shared.b16 {%0,%1,%2,%3}, [%4];"
                 : "=r"(r[0]), "=r"(r[1]), "=r"(r[2]), "=r"(r[3]) : "r"(addr));
}
__device__ __forceinline__ void ldsm4t(unsigned* r, uint32_t addr) {
    asm volatile("ldmatrix.sync.aligned.m8n8.x4.trans.shared.b16 {%0,%1,%2,%3}, [%4];"
                 : "=r"(r[0]), "=r"(r[1]), "=r"(r[2]), "=r"(r[3]) : "r"(addr));
}
__device__ __forceinline__ void mma_bf16(float* d, const unsigned* a, const unsigned* b) {
    asm volatile(
        "mma.sync.aligned.m16n8k16.row.col.f32.bf16.bf16.f32 "
        "{%0,%1,%2,%3}, {%4,%5,%6,%7}, {%8,%9}, {%0,%1,%2,%3};"
        : "+f"(d[0]), "+f"(d[1]), "+f"(d[2]), "+f"(d[3])
        : "r"(a[0]), "r"(a[1]), "r"(a[2]), "r"(a[3]), "r"(b[0]), "r"(b[1]));
}
__device__ __forceinline__ void mma_bf16_2(float* d, const unsigned* a,
                                           unsigned b0, unsigned b1) {
    asm volatile(
        "mma.sync.aligned.m16n8k16.row.col.f32.bf16.bf16.f32 "
        "{%0,%1,%2,%3}, {%4,%5,%6,%7}, {%8,%9}, {%0,%1,%2,%3};"
        : "+f"(d[0]), "+f"(d[1]), "+f"(d[2]), "+f"(d[3])
        : "r"(a[0]), "r"(a[1]), "r"(a[2]), "r"(a[3]), "r"(b0), "r"(b1));
}
__device__ __forceinline__ void cp16(uint32_t dst, const void* src) {
    asm volatile("cp.async.cg.shared.global [%0], [%1], 16;"
                 :: "r"(dst), "l"(src) : "memory");
}
__device__ __forceinline__ void cp_commit() {
    asm volatile("cp.async.commit_group;" ::: "memory");
}
__device__ __forceinline__ void cp_wait1() {
    asm volatile("cp.async.wait_group 1;" ::: "memory");
}
__device__ __forceinline__ void cp_wait0() {
    asm volatile("cp.async.wait_group 0;" ::: "memory");
}

// ---------------- zero accumulators + padded-array halos ----------------------
__global__ void zero_kernel() {
    int n = BB*CC_*KK;
    for (int i = blockIdx.x*blockDim.x + threadIdx.x; i < n; i += gridDim.x*blockDim.x)
        g_attn[i] = 0.f;
    const __nv_bfloat16 z = __float2bfloat16(0.f);
    int hn = BB*CC_*2128;
    for (int idx = blockIdx.x*blockDim.x + threadIdx.x; idx < hn;
         idx += gridDim.x*blockDim.x) {
        int plane = idx / 2128, e = idx - plane*2128;
        int row, px;
        if (e < 400) { row = (e < 200) ? 0 : 193; px = (e < 200) ? e : e - 200; }
        else { int e2 = e - 400; row = 1 + e2/9; int i9 = e2 - (e2/9)*9;
               px = (i9 < 2) ? i9 : 189 + i9; }   // 0,1,191..197
        size_t off = (size_t)plane*PLANE + row*WP + px;
        g_paa_h[off] = z; g_paa_l[off] = z;
        g_pab_h[off] = z; g_pab_l[off] = z;
        g_pac_h[off] = z; g_pac_l[off] = z;
    }
    if (blockIdx.x == 0 && threadIdx.x < CC_) {
        g_sum[threadIdx.x] = 0.f;
        g_sumsq[threadIdx.x] = 0.f;
    }
}

// ---------------- split x into padded bf16 hi/lo copies (3 shifts) ------------
__global__ void split_x_pad_kernel(const float* __restrict__ x) {
    for (size_t idx = (size_t)blockIdx.x*blockDim.x + threadIdx.x; idx < (size_t)PTOT;
         idx += (size_t)gridDim.x*blockDim.x) {
        size_t bc = idx / PLANE;
        int p  = (int)(idx - bc*PLANE);
        int py = p / WP, px = p - py*WP;
        int yy = py - 1;
        float vA = 0.f, vB = 0.f, vC = 0.f;
        if ((unsigned)yy < HH) {
            const float* row = x + bc*HW + (size_t)yy*WW;
            if ((unsigned)(px - 1) < WW) vA = row[px - 1];
            if ((unsigned)px < WW)       vB = row[px];
            if ((unsigned)(px + 1) < WW) vC = row[px + 1];
        }
        __nv_bfloat16 hA = __float2bfloat16(vA);
        g_pxa_h[idx] = hA;
        g_pxa_l[idx] = __float2bfloat16(vA - __bfloat162float(hA));
        __nv_bfloat16 hB = __float2bfloat16(vB);
        g_pxb_h[idx] = hB;
        g_pxb_l[idx] = __float2bfloat16(vB - __bfloat162float(hB));
        __nv_bfloat16 hC = __float2bfloat16(vC);
        g_pxc_h[idx] = hC;
        g_pxc_l[idx] = __float2bfloat16(vC - __bfloat162float(hC));
    }
}

// ---------------- split static weights (permuted k: knew=(r*3+dx)*128+ic) -----
__global__ void split_w_kernel(const float* __restrict__ w1,
                               const float* __restrict__ w2,
                               const float* __restrict__ w3) {
    const float* w = (blockIdx.y == 0) ? w1 : (blockIdx.y == 1) ? w2 : w3;
    int base = blockIdx.y * CC_ * KK;
    for (int e = blockIdx.x*blockDim.x + threadIdx.x; e < CC_*KK;
         e += gridDim.x*blockDim.x) {
        int o = e / KK, knew = e - o*KK;
        int rr = knew >> 7, ic = knew & 127;
        float v = w[(size_t)o*KK + ic*9 + rr];
        __nv_bfloat16 h = __float2bfloat16(v);
        g_wh[base + e] = h;
        g_wl[base + e] = __float2bfloat16(v - __bfloat162float(h));
    }
}

// ---------------- bf16 tensor-core implicit-GEMM 3x3 conv ---------------------
// CTA: M=128 o x N=96 px. K=1152 in 36 chunks of 32, (r,dx)-major.
// 3-stage cp.async pipeline. B fill = 3 cp16/thread via 3-shift padded copies.
// Inner loop interleaves per-n-group LDSM with MMA.
#define A_STRIDE 80
#define B_STRIDE 208
#define A_BYTES (128*A_STRIDE)
#define B_BYTES (32*B_STRIDE)
#define STG (2*A_BYTES + 2*B_BYTES)
#define SMEM_CONV (3*STG)

__global__ __launch_bounds__(256, 2) void conv_mma_kernel(
    const __nv_bfloat16* __restrict__ pA_h, const __nv_bfloat16* __restrict__ pA_l,
    const __nv_bfloat16* __restrict__ pB_h, const __nv_bfloat16* __restrict__ pB_l,
    const __nv_bfloat16* __restrict__ pC_h, const __nv_bfloat16* __restrict__ pC_l,
    const __nv_bfloat16* __restrict__ wh_g, const __nv_bfloat16* __restrict__ wl_g,
    long wbstride, void* __restrict__ p0, void* __restrict__ p1,
    void* __restrict__ p2, void* __restrict__ p3,
    void* __restrict__ p4, void* __restrict__ p5, int mode)
{
    extern __shared__ __align__(16) unsigned char smem[];
    const int b  = blockIdx.z;
    const int y  = blockIdx.y;
    const int x0 = blockIdx.x * 96;
    const int tid = threadIdx.x;
    const int lane = tid & 31, wid = tid >> 5;
    const int wm = wid & 3, wn = wid >> 2;
    const uint32_t sb = smem_u32(smem);

    const __nv_bfloat16* pah = pA_h + (size_t)b*PCHW;
    const __nv_bfloat16* pal = pA_l + (size_t)b*PCHW;
    const __nv_bfloat16* pbh = pB_h + (size_t)b*PCHW;
    const __nv_bfloat16* pbl = pB_l + (size_t)b*PCHW;
    const __nv_bfloat16* pch = pC_h + (size_t)b*PCHW;
    const __nv_bfloat16* pcl = pC_l + (size_t)b*PCHW;
    const __nv_bfloat16* wh = wh_g + (size_t)b*wbstride;
    const __nv_bfloat16* wl = wl_g + (size_t)b*wbstride;

    // B fill: 768 cp16 slots (32 rows x 12 x hi/lo)
    int bsrc[3], bdst[3], bhl[3];
#pragma unroll
    for (int i = 0; i < 3; i++) {
        int slot = tid + i*256;              // < 768
        int hl = slot >= 384;
        int rem = slot - hl*384;
        int rowt = rem / 12, np8 = rem - rowt*12;
        bsrc[i] = rowt*PLANE + np8*8;
        bdst[i] = hl*B_BYTES + rowt*B_STRIDE + np8*16;
        bhl[i]  = hl;
    }
    int adst[4], aoff[4];
#pragma unroll
    for (int i = 0; i < 4; i++) {
        int slot = tid + i*256;
        int rem = slot & 511;
        int o = rem >> 2, qq = rem & 3;
        adst[i] = (slot >> 9)*A_BYTES + o*A_STRIDE + qq*16;
        aoff[i] = o*KK + qq*8;
    }

    float acc[2][6][4];
#pragma unroll
    for (int mh = 0; mh < 2; mh++)
#pragma unroll
        for (int j = 0; j < 6; j++)
#pragma unroll
            for (int t = 0; t < 4; t++) acc[mh][j][t] = 0.f;

    auto loadAB = [&](int c) {
        const uint32_t stg = sb + (c % 3)*STG;
        const int kofs = c*32;
#pragma unroll
        for (int i = 0; i < 2; i++) cp16(stg + adst[i], wh + aoff[i] + kofs);
#pragma unroll
        for (int i = 2; i < 4; i++) cp16(stg + adst[i], wl + aoff[i] + kofs);
        int r = c / 12, t = c - r*12;
        int dx = t >> 2, q = t & 3;
        int ibase = q*32*PLANE + (y + r)*WP + x0;
        const __nv_bfloat16* hp = (dx == 0 ? pah : (dx == 1 ? pbh : pch)) + ibase;
        const __nv_bfloat16* lp = (dx == 0 ? pal : (dx == 1 ? pbl : pcl)) + ibase;
        const uint32_t bb = stg + 2*A_BYTES;
#pragma unroll
        for (int i = 0; i < 3; i++)
            cp16(bb + bdst[i], (bhl[i] ? lp : hp) + bsrc[i]);
        cp_commit();
    };

    loadAB(0);
    loadAB(1);

    for (int c = 0; c < 36; c++) {
        if (c < 34) cp_wait1(); else cp_wait0();
        __syncthreads();
        if (c < 34) loadAB(c + 2);

        const uint32_t stg = sb + (c % 3)*STG;
        const uint32_t Ah_s = stg;
        const uint32_t Al_s = stg + A_BYTES;
        const uint32_t Bh_s = stg + 2*A_BYTES;
        const uint32_t Bl_s = Bh_s + B_BYTES;
#pragma unroll
        for (int st = 0; st < 2; st++) {
            unsigned Ah[2][4], Al[2][4];
#pragma unroll
            for (int mh = 0; mh < 2; mh++) {
                uint32_t off = (uint32_t)(wm*32 + mh*16 + (lane & 15))*A_STRIDE
                             + ((lane >> 4) << 4) + st*32;
                ldsm4(Ah[mh], Ah_s + off);
                ldsm4(Al[mh], Al_s + off);
            }
#pragma unroll
            for (int nf = 0; nf < 3; nf++) {
                unsigned Bh[4], Bl[4];
                uint32_t off = (uint32_t)(st*16 + (lane & 15))*B_STRIDE
                             + wn*96 + nf*32 + ((lane >> 4) << 4);
                ldsm4t(Bh, Bh_s + off);
                ldsm4t(Bl, Bl_s + off);
#pragma unroll
                for (int mh = 0; mh < 2; mh++) {
#pragma unroll
                    for (int jj = 0; jj < 2; jj++) {
                        float* a = acc[mh][nf*2 + jj];
                        const unsigned* bh = &Bh[jj*2];
                        const unsigned* bl = &Bl[jj*2];
                        mma_bf16(a, Ah[mh], bh);
                        mma_bf16(a, Ah[mh], bl);
                        mma_bf16(a, Al[mh], bh);
                    }
                }
            }
        }
    }

    // ---- epilogue ----
    if (mode == 0) {
        float* out = (float*)p0;
#pragma unroll
        for (int mh = 0; mh < 2; mh++) {
            int o = wm*32 + mh*16 + (lane >> 2);
#pragma unroll
            for (int j = 0; j < 6; j++) {
                int x = x0 + wn*48 + j*8 + (lane & 3)*2;
                size_t i0 = ((size_t)b*CC_ + o)*HW + (size_t)y*WW + x;
                size_t i1 = i0 + (size_t)8*HW;
                *(float2*)(out + i0) = make_float2(acc[mh][j][0], acc[mh][j][1]);
                *(float2*)(out + i1) = make_float2(acc[mh][j][2], acc[mh][j][3]);
            }
        }
    } else if (mode == 1) {
        // stage: h/l planes, stride 100 per ch, +1 element shift
        __syncthreads();
        __nv_bfloat16* sh = (__nv_bfloat16*)smem;      // 128*100
        __nv_bfloat16* sl = sh + 12800;
#pragma unroll
        for (int mh = 0; mh < 2; mh++) {
            int o = wm*32 + mh*16 + (lane >> 2);
#pragma unroll
            for (int j = 0; j < 6; j++) {
                int xb = wn*48 + j*8 + (lane & 3)*2;
#pragma unroll
                for (int t = 0; t < 4; t++) {
                    int oo = o + (t >> 1)*8;
                    int xx = xb + (t & 1);
                    float v = acc[mh][j][t];
                    __nv_bfloat16 h = __float2bfloat16(v);
                    int si = oo*100 + xx + 1;
                    sh[si] = h;
                    sl[si] = __float2bfloat16(v - __bfloat162float(h));
                }
            }
        }
        __syncthreads();
        // write 6 padded arrays: a=0,1 -> shiftA(h,l); 2,3 -> shiftB; 4,5 -> shiftC
        for (int run = wid; run < 768; run += 8) {
            int a = run >> 7, ch = run & 127;
            const __nv_bfloat16* sp = ((a & 1) ? sl : sh) + ch*100;
            __nv_bfloat16* base =
                (a == 0) ? (__nv_bfloat16*)p0 : (a == 1) ? (__nv_bfloat16*)p1 :
                (a == 2) ? (__nv_bfloat16*)p2 : (a == 3) ? (__nv_bfloat16*)p3 :
                (a == 4) ? (__nv_bfloat16*)p4 : (__nv_bfloat16*)p5;
            size_t rb = ((size_t)b*CC_ + ch)*PLANE + (size_t)(y + 1)*WP + x0;
            if (a >= 2 && a < 4) {
                // shift B: even-aligned, value(x) at px=x
                __nv_bfloat16* dst = base + rb;
                for (int j2 = lane; j2 < 48; j2 += 32) {
                    uint32_t lo2 = (uint32_t)*(const unsigned short*)(sp + 1 + 2*j2);
                    uint32_t hi2 = (uint32_t)*(const unsigned short*)(sp + 2 + 2*j2);
                    *(uint32_t*)(dst + 2*j2) = lo2 | (hi2 << 16);
                }
            } else {
                // shift A (+1) / shift C (-1): odd-aligned runs
                int offp = (a < 2) ? 1 : -1;
                __nv_bfloat16* dst = base + rb + offp;
                if (lane == 0 && !(a >= 4 && x0 == 0)) dst[0] = sp[1];
                if (lane == 1) dst[95] = sp[96];
                for (int j2 = lane; j2 < 47; j2 += 32) {
                    uint32_t v = *(const uint32_t*)(sp + 2 + 2*j2);
                    *(uint32_t*)(dst + 1 + 2*j2) = v;
                }
            }
        }
    } else {
        // stage: h/l planes in packed order [ch][cx*32+qx], then uint4 stores
        __syncthreads();
        __nv_bfloat16* sh = (__nv_bfloat16*)smem;      // 128*96
        __nv_bfloat16* sl = sh + 12288;
#pragma unroll
        for (int mh = 0; mh < 2; mh++) {
            int o = wm*32 + mh*16 + (lane >> 2);
#pragma unroll
            for (int j = 0; j < 6; j++) {
                int xb = wn*48 + j*8 + (lane & 3)*2;
#pragma unroll
                for (int t = 0; t < 4; t++) {
                    int oo = o + (t >> 1)*8;
                    int xx = xb + (t & 1);
                    int qx = xx / 3;
                    int cx = xx - qx*3;
                    float v = acc[mh][j][t];
                    __nv_bfloat16 h = __float2bfloat16(v);
                    int si = oo*96 + cx*32 + qx;
                    sh[si] = h;
                    sl[si] = __float2bfloat16(v - __bfloat162float(h));
                }
            }
        }
        __syncthreads();
        __nv_bfloat16* ph = (__nv_bfloat16*)p0;
        __nv_bfloat16* pl = (__nv_bfloat16*)p1;
        int cy = y % 3, qy = y / 3;
        int bx32 = blockIdx.x * 32;
#pragma unroll
        for (int i = 0; i < 12; i++) {
            int s = tid + i*256;          // < 3072
            int seg = s >> 2, q = s & 3;
            int ch = seg / 6, r6 = seg - ch*6;
            int cx = r6 >> 1, hl = r6 & 1;
            const uint4* src = (const uint4*)((hl ? sl : sh) + ch*96 + cx*32 + q*8);
            __nv_bfloat16* dst = (hl ? pl : ph)
                + (((size_t)b*CC_ + ch)*9 + cy*3 + cx)*4096 + qy*64 + bx32 + q*8;
            *(uint4*)dst = *src;
        }
    }
}

// ---------------- tensor-core attention correlation GEMM ----------------------
#define AT_STRIDE 80
#define AT_BYTES (128*AT_STRIDE)   // 10240
#define AT_STG (4*AT_BYTES)        // 40960
#define SMEM_ATTN (2*AT_STG)       // 81920

__global__ __launch_bounds__(256, 2) void attn_mma_kernel(
    const __nv_bfloat16* __restrict__ a1h, const __nv_bfloat16* __restrict__ a1l,
    const __nv_bfloat16* __restrict__ a2h, const __nv_bfloat16* __restrict__ a2l)
{
    extern __shared__ __align__(16) unsigned char smem[];
    const int ks  = blockIdx.x;
    const int cls = blockIdx.y;
    const int b   = blockIdx.z;
    const int tid = threadIdx.x;
    const int lane = tid & 31, wid = tid >> 5;
    const int wm = wid & 3, wn = wid >> 2;
    const uint32_t sb = smem_u32(smem);

    const size_t cbase = ((size_t)b*CC_*9 + cls)*4096 + ks*1024;
    const __nv_bfloat16* Ah_g = a2h + cbase;
    const __nv_bfloat16* Al_g = a2l + cbase;
    const __nv_bfloat16* Bh_g = a1h + cbase;
    const __nv_bfloat16* Bl_g = a1l + cbase;

    int sdst[4];
    size_t ssrc[4];
#pragma unroll
    for (int i = 0; i < 4; i++) {
        int slot = tid + i*256;
        int r = (slot & 511) >> 2, q = slot & 3;
        sdst[i] = (slot >> 9)*AT_BYTES + r*AT_STRIDE + q*16;
        ssrc[i] = (size_t)r*36864 + q*8;
    }

    float acc[2][8][4];
#pragma unroll
    for (int mh = 0; mh < 2; mh++)
#pragma unroll
        for (int nj = 0; nj < 8; nj++)
#pragma unroll
            for (int t = 0; t < 4; t++) acc[mh][nj][t] = 0.f;

    auto loadAB = [&](int c) {
        const uint32_t stg = sb + (c & 1)*AT_STG;
        const int kofs = c*32;
#pragma unroll
        for (int i = 0; i < 2; i++) cp16(stg + sdst[i], Ah_g + ssrc[i] + kofs);
#pragma unroll
        for (int i = 2; i < 4; i++) cp16(stg + sdst[i], Al_g + ssrc[i] + kofs);
#pragma unroll
        for (int i = 0; i < 2; i++)
            cp16(stg + 2*AT_BYTES + sdst[i], Bh_g + ssrc[i] + kofs);
#pragma unroll
        for (int i = 2; i < 4; i++)
            cp16(stg + 2*AT_BYTES + sdst[i], Bl_g + ssrc[i] + kofs);
        cp_commit();
    };

    loadAB(0);
    for (int c = 0; c < 32; c++) {
        cp_wait0();
        __syncthreads();
        if (c < 31) loadAB(c + 1);

        const uint32_t stg = sb + (c & 1)*AT_STG;
        const uint32_t Ah_s = stg;
        const uint32_t Al_s = stg + AT_BYTES;
        const uint32_t Bh_s = stg + 2*AT_BYTES;
        const uint32_t Bl_s = stg + 3*AT_BYTES;
#pragma unroll
        for (int st = 0; st < 2; st++) {
            unsigned Ah[2][4], Al[2][4];
#pragma unroll
            for (int mh = 0; mh < 2; mh++) {
                uint32_t off = (uint32_t)(wm*32 + mh*16 + (lane & 15))*AT_STRIDE
                             + ((lane >> 4) << 4) + st*32;
                ldsm4(Ah[mh], Ah_s + off);
                ldsm4(Al[mh], Al_s + off);
            }
#pragma unroll
            for (int ng = 0; ng < 4; ng++) {
                uint32_t off = (uint32_t)(wn*64 + ng*16 + (lane & 7)
                             + ((lane >> 3) & 1)*8)*AT_STRIDE
                             + st*32 + ((lane >> 4) & 1)*16;
                unsigned Bh[4], Bl[4];
                ldsm4(Bh, Bh_s + off);
                ldsm4(Bl, Bl_s + off);
#pragma unroll
                for (int mh = 0; mh < 2; mh++) {
#pragma unroll
                    for (int s2 = 0; s2 < 2; s2++) {
                        float* a = acc[mh][ng*2 + s2];
                        mma_bf16_2(a, Ah[mh], Bh[s2], Bh[s2 + 2]);
                        mma_bf16_2(a, Ah[mh], Bl[s2], Bl[s2 + 2]);
                        mma_bf16_2(a, Al[mh], Bh[s2], Bh[s2 + 2]);
                    }
                }
            }
        }
    }

#pragma unroll
    for (int mh = 0; mh < 2; mh++) {
        int o0 = wm*32 + mh*16 + (lane >> 2);
#pragma unroll
        for (int nj = 0; nj < 8; nj++) {
            int n0 = wn*64 + nj*8 + (lane & 3)*2;
            size_t r0 = ((size_t)b*CC_ + o0)*KK;
            size_t r1 = ((size_t)b*CC_ + o0 + 8)*KK;
            atomicAdd(&g_attn[r0 + (size_t)n0*9 + cls],       acc[mh][nj][0]);
            atomicAdd(&g_attn[r0 + (size_t)(n0 + 1)*9 + cls], acc[mh][nj][1]);
            atomicAdd(&g_attn[r1 + (size_t)n0*9 + cls],       acc[mh][nj][2]);
            atomicAdd(&g_attn[r1 + (size_t)(n0 + 1)*9 + cls], acc[mh][nj][3]);
        }
    }
}

// ---------------- softmax; emits dynamic kernels as bf16 hi/lo, permuted k ----
__global__ __launch_bounds__(256) void softmax_kernel() {
    __shared__ float red[256];
    const int row = blockIdx.x;
    const float* rp = g_attn + (size_t)row*KK;
    const float scale = 0.029462782549439483f;
    const int tid = threadIdx.x;

    float m = -1e30f;
    for (int e = tid; e < KK; e += 256) m = fmaxf(m, rp[e]);
    red[tid] = m; __syncthreads();
    for (int s = 128; s > 0; s >>= 1) {
        if (tid < s) red[tid] = fmaxf(red[tid], red[tid + s]);
        __syncthreads();
    }
    m = red[0] * scale;
    __syncthreads();

    float sum = 0.f;
    for (int e = tid; e < KK; e += 256) sum += expf(rp[e]*scale - m);
    red[tid] = sum; __syncthreads();
    for (int s = 128; s > 0; s >>= 1) {
        if (tid < s) red[tid] += red[tid + s];
        __syncthreads();
    }
    float inv = 1.f / red[0];

    for (int e = tid; e < KK; e += 256) {
        float p = expf(rp[e]*scale - m) * inv;
        int i = e / 9, rr = e - i*9;
        int knew = rr*128 + i;
        __nv_bfloat16 h = __float2bfloat16(p);
        g_kh[(size_t)row*KK + knew] = h;
        g_kl[(size_t)row*KK + knew] = __float2bfloat16(p - __bfloat162float(h));
    }
}

// ---------------- BN stats over av partitioned by (group, parity) ------------
__global__ __launch_bounds__(256) void stats_kernel() {
    const int g = blockIdx.x;
    const int b = blockIdx.y;
    const int tid = threadIdx.x;
    float s00=0,s01=0,s10=0,s11=0,q00=0,q01=0,q10=0,q11=0;
    for (int c = 0; c < 4; c++) {
        const float* p = g_av + ((size_t)b*CC_ + g*4 + c)*HW;
        for (int e = tid; e < HW/2; e += 256) {
            int y = e / 96;
            int x2 = (e - y*96) * 2;
            float v0 = p[y*WW + x2];
            float v1 = p[y*WW + x2 + 1];
            if (y & 1) { s10 += v0; q10 += v0*v0; s11 += v1; q11 += v1*v1; }
            else       { s00 += v0; q00 += v0*v0; s01 += v1; q01 += v1*v1; }
        }
    }
    __shared__ float red[256];
    float vals[8] = {s00, s01, s10, s11, q00, q01, q10, q11};
#pragma unroll
    for (int v = 0; v < 8; v++) {
        red[tid] = vals[v]; __syncthreads();
        for (int st = 128; st > 0; st >>= 1) {
            if (tid < st) red[tid] += red[tid + st];
            __syncthreads();
        }
        if (tid == 0) {
            int p2 = v & 3;
            if (v < 4) atomicAdd(&g_sum[g*4 + p2],   red[0]);
            else       atomicAdd(&g_sumsq[g*4 + p2], red[0]);
        }
        __syncthreads();
    }
}

__global__ void finalize_kernel() {
    int c = threadIdx.x;
    if (c < CC_) {
        float n = (float)STAT_N;
        float mean = g_sum[c] / n;
        float var  = g_sumsq[c] / n - mean*mean;
        g_mean[c] = mean;
        g_inv[c]  = NORM_SCALE * rsqrtf(var + EPSV);
    }
}

// ---------------- fused stack-gather + BN + residual epilogue ----------------
__global__ __launch_bounds__(256) void output_kernel(const float* __restrict__ x,
                                                     const float* __restrict__ mom_p,
                                                     float* __restrict__ out) {
    const float mom = *mom_p;
    for (size_t idx = (size_t)blockIdx.x*blockDim.x + threadIdx.x; idx < (size_t)TOT;
         idx += (size_t)gridDim.x*blockDim.x) {
        size_t b = idx / CHW;
        int r  = (int)(idx - b*CHW);
        int c2 = r / HW;
        int rr = r - c2*HW;
        int Y = rr / WW, X = rr - Y*WW;
        int i2 = (Y >= 96), j2 = (X >= 96);
        int ph = Y - i2*96, pw = X - j2*96;
        int sc = (c2 & ~3) | (i2*2 + j2);
        int sy = ph*2 + ((c2 >> 1) & 1);
        int sx = pw*2 + (c2 & 1);
        float v = g_av[((size_t)b*CC_ + sc)*HW + (size_t)sy*WW + sx];
        out[idx] = mom * x[idx] + (v - g_mean[c2]) * g_inv[c2];
    }
}

// ---------------- launch -----------------------------------------------------
extern "C" void kernel_launch(void* const* d_in, const int* in_sizes, int n_in,
                              void* d_out, int out_size) {
    const float* x   = (const float*)d_in[0];
    const float* w1  = (const float*)d_in[1];
    const float* w2  = (const float*)d_in[2];
    const float* w3  = (const float*)d_in[3];
    const float* mom = (const float*)d_in[4];
    float* out = (float*)d_out;

    cudaFuncSetAttribute(conv_mma_kernel,
                         cudaFuncAttributeMaxDynamicSharedMemorySize, SMEM_CONV);
    cudaFuncSetAttribute(attn_mma_kernel,
                         cudaFuncAttributeMaxDynamicSharedMemorySize, SMEM_ATTN);

    __nv_bfloat16 *pxa_h, *pxa_l, *pxb_h, *pxb_l, *pxc_h, *pxc_l;
    __nv_bfloat16 *paa_h, *paa_l, *pab_h, *pab_l, *pac_h, *pac_l;
    __nv_bfloat16 *a1p_h, *a1p_l, *a2p_h, *a2p_l;
    __nv_bfloat16 *wh, *wl, *kh, *kl;
    float *av;
    cudaGetSymbolAddress((void**)&pxa_h, g_pxa_h);
    cudaGetSymbolAddress((void**)&pxa_l, g_pxa_l);
    cudaGetSymbolAddress((void**)&pxb_h, g_pxb_h);
    cudaGetSymbolAddress((void**)&pxb_l, g_pxb_l);
    cudaGetSymbolAddress((void**)&pxc_h, g_pxc_h);
    cudaGetSymbolAddress((void**)&pxc_l, g_pxc_l);
    cudaGetSymbolAddress((void**)&paa_h, g_paa_h);
    cudaGetSymbolAddress((void**)&paa_l, g_paa_l);
    cudaGetSymbolAddress((void**)&pab_h, g_pab_h);
    cudaGetSymbolAddress((void**)&pab_l, g_pab_l);
    cudaGetSymbolAddress((void**)&pac_h, g_pac_h);
    cudaGetSymbolAddress((void**)&pac_l, g_pac_l);
    cudaGetSymbolAddress((void**)&a1p_h, g_a1p_h);
    cudaGetSymbolAddress((void**)&a1p_l, g_a1p_l);
    cudaGetSymbolAddress((void**)&a2p_h, g_a2p_h);
    cudaGetSymbolAddress((void**)&a2p_l, g_a2p_l);
    cudaGetSymbolAddress((void**)&av,  g_av);
    cudaGetSymbolAddress((void**)&wh,  g_wh);
    cudaGetSymbolAddress((void**)&wl,  g_wl);
    cudaGetSymbolAddress((void**)&kh,  g_kh);
    cudaGetSymbolAddress((void**)&kl,  g_kl);

    zero_kernel<<<2048, 256>>>();
    split_x_pad_kernel<<<8192, 256>>>(x);
    split_w_kernel<<<dim3(144, 3), 256>>>(w1, w2, w3);

    dim3 cgrid(2, HH, BB);
    conv_mma_kernel<<<cgrid, 256, SMEM_CONV>>>(pxa_h, pxa_l, pxb_h, pxb_l, pxc_h, pxc_l,
        wh + 0*(size_t)CC_*KK, wl + 0*(size_t)CC_*KK, 0,
        a1p_h, a1p_l, nullptr, nullptr, nullptr, nullptr, 2);
    conv_mma_kernel<<<cgrid, 256, SMEM_CONV>>>(pxa_h, pxa_l, pxb_h, pxb_l, pxc_h, pxc_l,
        wh + 1*(size_t)CC_*KK, wl + 1*(size_t)CC_*KK, 0,
        a2p_h, a2p_l, nullptr, nullptr, nullptr, nullptr, 2);
    conv_mma_kernel<<<cgrid, 256, SMEM_CONV>>>(pxa_h, pxa_l, pxb_h, pxb_l, pxc_h, pxc_l,
        wh + 2*(size_t)CC_*KK, wl + 2*(size_t)CC_*KK, 0,
        paa_h, paa_l, pab_h, pab_l, pac_h, pac_l, 1);

    attn_mma_kernel<<<dim3(4, 9, BB), 256, SMEM_ATTN>>>(a1p_h, a1p_l, a2p_h, a2p_l);
    softmax_kernel<<<BB*CC_, 256>>>();

    conv_mma_kernel<<<cgrid, 256, SMEM_CONV>>>(paa_h, paa_l, pab_h, pab_l, pac_h, pac_l,
        kh, kl, (long)CC_*KK, av, nullptr, nullptr, nullptr, nullptr, nullptr, 0);

    stats_kernel<<<dim3(32, 8), 256>>>();
    finalize_kernel<<<1, 128>>>();
    output_kernel<<<8192, 256>>>(x, mom, out);
}

// round 12
// speedup vs baseline: 1.0201x; 1.0201x over previous
#include <cuda_runtime.h>
#include <cuda_bf16.h>
#include <cstdint>

#define BB 8
#define CC_ 128
#define HH 192
#define WW 192
#define HW (HH*WW)
#define CHW (CC_*HW)
#define TOT (BB*CHW)
#define KK 1152            // C*9
#define CK (CC_*KK)        // 147456
#define EPSV 1e-5f
#define NORM_SCALE 0.1816f
#define STAT_N (BB*4*(HH/2)*(WW/2))   // 294912

// padded image geometry (1-px halo + alignment tail)
#define WP 200
#define HP 194
#define PLANE (HP*WP)          // 38800
#define PCHW (CC_*PLANE)
#define PTOT (BB*PCHW)

// ---------------- scratch (device globals; hi block then lo block) ------------
__device__ __align__(16) __nv_bfloat16 g_pxe[2*PTOT];   // aligned shift (dx 0/2)
__device__ __align__(16) __nv_bfloat16 g_pxo[2*PTOT];   // odd shift (dx 1)
__device__ __align__(16) __nv_bfloat16 g_pae[2*PTOT];
__device__ __align__(16) __nv_bfloat16 g_pao[2*PTOT];
__device__ __align__(16) __nv_bfloat16 g_a1p[2*(size_t)TOT];  // parity-packed
__device__ __align__(16) __nv_bfloat16 g_a2p[2*(size_t)TOT];
__device__ float g_av[TOT];
__device__ __align__(16) __nv_bfloat16 g_w[6*CK];       // [hi:3xCK][lo:3xCK]
__device__ __align__(16) __nv_bfloat16 g_k[2*BB*CK];    // [hi:BBxCK][lo:BBxCK]
__device__ float g_attn[BB*CC_*KK];
__device__ float g_sum[CC_];
__device__ float g_sumsq[CC_];
__device__ float g_mean[CC_];
__device__ float g_inv[CC_];

// ---------------- PTX helpers -------------------------------------------------
__device__ __forceinline__ uint32_t smem_u32(const void* p) {
    uint32_t a;
    asm("{ .reg .u64 t; cvta.to.shared.u64 t, %1; cvt.u32.u64 %0, t; }"
        : "=r"(a) : "l"(p));
    return a;
}
__device__ __forceinline__ void ldsm4(unsigned* r, uint32_t addr) {
    asm volatile("ldmatrix.sync.aligned.m8n8.x4.shared.b16 {%0,%1,%2,%3}, [%4];"
                 : "=r"(r[0]), "=r"(r[1]), "=r"(r[2]), "=r"(r[3]) : "r"(addr));
}
__device__ __forceinline__ void ldsm4t(unsigned* r, uint32_t addr) {
    asm volatile("ldmatrix.sync.aligned.m8n8.x4.trans.shared.b16 {%0,%1,%2,%3}, [%4];"
                 : "=r"(r[0]), "=r"(r[1]), "=r"(r[2]), "=r"(r[3]) : "r"(addr));
}
__device__ __forceinline__ void mma_bf16(float* d, const unsigned* a, const unsigned* b) {
    asm volatile(
        "mma.sync.aligned.m16n8k16.row.col.f32.bf16.bf16.f32 "
        "{%0,%1,%2,%3}, {%4,%5,%6,%7}, {%8,%9}, {%0,%1,%2,%3};"
        : "+f"(d[0]), "+f"(d[1]), "+f"(d[2]), "+f"(d[3])
        : "r"(a[0]), "r"(a[1]), "r"(a[2]), "r"(a[3]), "r"(b[0]), "r"(b[1]));
}
__device__ __forceinline__ void mma_bf16_2(float* d, const unsigned* a,
                                           unsigned b0, unsigned b1) {
    asm volatile(
        "mma.sync.aligned.m16n8k16.row.col.f32.bf16.bf16.f32 "
        "{%0,%1,%2,%3}, {%4,%5,%6,%7}, {%8,%9}, {%0,%1,%2,%3};"
        : "+f"(d[0]), "+f"(d[1]), "+f"(d[2]), "+f"(d[3])
        : "r"(a[0]), "r"(a[1]), "r"(a[2]), "r"(a[3]), "r"(b0), "r"(b1));
}
__device__ __forceinline__ void cp16(uint32_t dst, const void* src) {
    asm volatile("cp.async.cg.shared.global [%0], [%1], 16;"
                 :: "r"(dst), "l"(src) : "memory");
}
__device__ __forceinline__ void cp4(uint32_t dst, const void* src) {
    asm volatile("cp.async.ca.shared.global [%0], [%1], 4;"
                 :: "r"(dst), "l"(src) : "memory");
}
__device__ __forceinline__ void cp_commit() {
    asm volatile("cp.async.commit_group;" ::: "memory");
}
__device__ __forceinline__ void cp_wait1() {
    asm volatile("cp.async.wait_group 1;" ::: "memory");
}
__device__ __forceinline__ void cp_wait0() {
    asm volatile("cp.async.wait_group 0;" ::: "memory");
}

// ---------------- zero accumulators + padded-array halos ----------------------
__global__ void zero_kernel() {
    int n = BB*CC_*KK;
    for (int i = blockIdx.x*blockDim.x + threadIdx.x; i < n; i += gridDim.x*blockDim.x)
        g_attn[i] = 0.f;
    const __nv_bfloat16 z = __float2bfloat16(0.f);
    int hn = BB*CC_*2128;
    for (int idx = blockIdx.x*blockDim.x + threadIdx.x; idx < hn;
         idx += gridDim.x*blockDim.x) {
        int plane = idx / 2128, e = idx - plane*2128;
        int row, px;
        if (e < 400) { row = (e < 200) ? 0 : 193; px = (e < 200) ? e : e - 200; }
        else { int e2 = e - 400; row = 1 + e2/9; int i9 = e2 - (e2/9)*9;
               px = (i9 < 2) ? i9 : 191 + i9; }
        size_t off = (size_t)plane*PLANE + row*WP + px;
        g_pae[off] = z; g_pae[off + PTOT] = z;
        g_pao[off] = z; g_pao[off + PTOT] = z;
    }
    if (blockIdx.x == 0 && threadIdx.x < CC_) {
        g_sum[threadIdx.x] = 0.f;
        g_sumsq[threadIdx.x] = 0.f;
    }
}

// ---------------- split x into padded bf16 hi/lo copies (aligned + shifted) ---
__global__ void split_x_pad_kernel(const float* __restrict__ x) {
    for (size_t idx = (size_t)blockIdx.x*blockDim.x + threadIdx.x; idx < (size_t)PTOT;
         idx += (size_t)gridDim.x*blockDim.x) {
        size_t bc = idx / PLANE;
        int p  = (int)(idx - bc*PLANE);
        int py = p / WP, px = p - py*WP;
        int yy = py - 1;
        float va = 0.f, vs = 0.f;
        if ((unsigned)yy < HH) {
            const float* row = x + bc*HW + (size_t)yy*WW;
            int xa = px - 1, xs = px - 2;
            if ((unsigned)xa < WW) va = row[xa];
            if ((unsigned)xs < WW) vs = row[xs];
        }
        __nv_bfloat16 ha = __float2bfloat16(va);
        g_pxe[idx] = ha;
        g_pxe[idx + PTOT] = __float2bfloat16(va - __bfloat162float(ha));
        __nv_bfloat16 hs = __float2bfloat16(vs);
        g_pxo[idx] = hs;
        g_pxo[idx + PTOT] = __float2bfloat16(vs - __bfloat162float(hs));
    }
}

// ---------------- split static weights (permuted k: knew=(r*3+dx)*128+ic) -----
__global__ void split_w_kernel(const float* __restrict__ w1,
                               const float* __restrict__ w2,
                               const float* __restrict__ w3) {
    const float* w = (blockIdx.y == 0) ? w1 : (blockIdx.y == 1) ? w2 : w3;
    int base = blockIdx.y * CK;
    for (int e = blockIdx.x*blockDim.x + threadIdx.x; e < CK;
         e += gridDim.x*blockDim.x) {
        int o = e / KK, knew = e - o*KK;
        int rr = knew >> 7, ic = knew & 127;
        float v = w[(size_t)o*KK + ic*9 + rr];
        __nv_bfloat16 h = __float2bfloat16(v);
        g_w[base + e] = h;
        g_w[3*CK + base + e] = __float2bfloat16(v - __bfloat162float(h));
    }
}

// ---------------- bf16 tensor-core implicit-GEMM 3x3 conv ---------------------
// CTA: M=128 o x N=96 px, 384 threads = 12 warps (4m x 3n), warp tile m32 x n32.
// K=1152 in 36 chunks of 32, (r,dx)-major. 3-stage cp.async pipeline.
#define A_STRIDE 80
#define B_STRIDE 208
#define A_BYTES (128*A_STRIDE)
#define B_BYTES (32*B_STRIDE)
#define STG (2*A_BYTES + 2*B_BYTES)
#define SMEM_CONV (3*STG)
#define NT 384

__global__ __launch_bounds__(NT, 2) void conv_mma_kernel(
    const __nv_bfloat16* __restrict__ pe, const __nv_bfloat16* __restrict__ po,
    const __nv_bfloat16* __restrict__ w_, long wlo, long wbstride,
    void* __restrict__ p0, void* __restrict__ p1, int mode)
{
    extern __shared__ __align__(16) unsigned char smem[];
    const int b  = blockIdx.z;
    const int y  = blockIdx.y;
    const int x0 = blockIdx.x * 96;
    const int tid = threadIdx.x;
    const int lane = tid & 31, wid = tid >> 5;
    const int wm = wid & 3, wn = wid >> 2;           // wn 0..2
    const uint32_t sb = smem_u32(smem);

    const __nv_bfloat16* peb = pe + (size_t)b*PCHW;
    const __nv_bfloat16* pob = po + (size_t)b*PCHW;
    const __nv_bfloat16* wh = w_ + (size_t)b*wbstride;

    // B fill: 1536 geometry slots (32 rows x 48 np), each does h+l cp4
    int bsrc[4], bdst[4];
#pragma unroll
    for (int i = 0; i < 4; i++) {
        int slot = tid + i*NT;               // < 1536
        int rowt = slot / 48, np = slot - rowt*48;
        bsrc[i] = rowt*PLANE + np*2;
        bdst[i] = rowt*B_STRIDE + np*4;
    }
    // A fill: 1024 cp16 slots
    int adst[3], ahl[3];
    long aoff[3];
#pragma unroll
    for (int i = 0; i < 3; i++) {
        int slot = tid + i*NT;               // < 1152, guard < 1024
        int hl = slot >> 9;
        int rem = slot & 511;
        int o = rem >> 2, qq = rem & 3;
        adst[i] = hl*A_BYTES + o*A_STRIDE + qq*16;
        aoff[i] = (long)o*KK + qq*8 + (hl ? wlo : 0);
        ahl[i]  = (slot < 1024);
    }

    float acc[2][4][4];
#pragma unroll
    for (int mh = 0; mh < 2; mh++)
#pragma unroll
        for (int j = 0; j < 4; j++)
#pragma unroll
            for (int t = 0; t < 4; t++) acc[mh][j][t] = 0.f;

    auto loadAB = [&](int c) {
        const uint32_t stg = sb + (c % 3)*STG;
        const int kofs = c*32;
#pragma unroll
        for (int i = 0; i < 3; i++)
            if (ahl[i]) cp16(stg + adst[i], wh + aoff[i] + kofs);
        int r = c / 12, t = c - r*12;
        int dx = t >> 2, q = t & 3;
        int ibase = q*32*PLANE + (y + r)*WP + x0 + dx + (dx == 1);
        const __nv_bfloat16* hp = ((dx == 1) ? pob : peb) + ibase;
        const uint32_t bb = stg + 2*A_BYTES;
#pragma unroll
        for (int i = 0; i < 4; i++) {
            cp4(bb + bdst[i],           hp + bsrc[i]);
            cp4(bb + B_BYTES + bdst[i], hp + PTOT + bsrc[i]);
        }
        cp_commit();
    };

    loadAB(0);
    loadAB(1);

    for (int c = 0; c < 36; c++) {
        if (c < 34) cp_wait1(); else cp_wait0();
        __syncthreads();
        if (c < 34) loadAB(c + 2);

        const uint32_t stg = sb + (c % 3)*STG;
        const uint32_t Ah_s = stg;
        const uint32_t Al_s = stg + A_BYTES;
        const uint32_t Bh_s = stg + 2*A_BYTES;
        const uint32_t Bl_s = Bh_s + B_BYTES;
#pragma unroll
        for (int st = 0; st < 2; st++) {
            unsigned Ah[2][4], Al[2][4];
#pragma unroll
            for (int mh = 0; mh < 2; mh++) {
                uint32_t off = (uint32_t)(wm*32 + mh*16 + (lane & 15))*A_STRIDE
                             + ((lane >> 4) << 4) + st*32;
                ldsm4(Ah[mh], Ah_s + off);
                ldsm4(Al[mh], Al_s + off);
            }
#pragma unroll
            for (int ng = 0; ng < 2; ng++) {
                unsigned Bh[4], Bl[4];
                uint32_t off = (uint32_t)(st*16 + (lane & 15))*B_STRIDE
                             + wn*64 + ng*32 + ((lane >> 4) << 4);
                ldsm4t(Bh, Bh_s + off);
                ldsm4t(Bl, Bl_s + off);
#pragma unroll
                for (int mh = 0; mh < 2; mh++) {
#pragma unroll
                    for (int jj = 0; jj < 2; jj++) {
                        float* a = acc[mh][ng*2 + jj];
                        const unsigned* bh = &Bh[jj*2];
                        const unsigned* bl = &Bl[jj*2];
                        mma_bf16(a, Ah[mh], bh);
                        mma_bf16(a, Ah[mh], bl);
                        mma_bf16(a, Al[mh], bh);
                    }
                }
            }
        }
    }

    // ---- epilogue ----
    if (mode == 0) {
        float* out = (float*)p0;
#pragma unroll
        for (int mh = 0; mh < 2; mh++) {
            int o = wm*32 + mh*16 + (lane >> 2);
#pragma unroll
            for (int j = 0; j < 4; j++) {
                int x = x0 + wn*32 + j*8 + (lane & 3)*2;
                size_t i0 = ((size_t)b*CC_ + o)*HW + (size_t)y*WW + x;
                size_t i1 = i0 + (size_t)8*HW;
                *(float2*)(out + i0) = make_float2(acc[mh][j][0], acc[mh][j][1]);
                *(float2*)(out + i1) = make_float2(acc[mh][j][2], acc[mh][j][3]);
            }
        }
    } else if (mode == 1) {
        // stage: h/l planes, stride 100 per ch, +1 element shift
        __syncthreads();
        __nv_bfloat16* sh = (__nv_bfloat16*)smem;      // 128*100
        __nv_bfloat16* sl = sh + 12800;
#pragma unroll
        for (int mh = 0; mh < 2; mh++) {
            int o = wm*32 + mh*16 + (lane >> 2);
#pragma unroll
            for (int j = 0; j < 4; j++) {
                int xb = wn*32 + j*8 + (lane & 3)*2;
#pragma unroll
                for (int t = 0; t < 4; t++) {
                    int oo = o + (t >> 1)*8;
                    int xx = xb + (t & 1);
                    float v = acc[mh][j][t];
                    __nv_bfloat16 h = __float2bfloat16(v);
                    int si = oo*100 + xx + 1;
                    sh[si] = h;
                    sl[si] = __float2bfloat16(v - __bfloat162float(h));
                }
            }
        }
        __syncthreads();
        __nv_bfloat16* eb = (__nv_bfloat16*)p0;   // pae (lo at +PTOT)
        __nv_bfloat16* ob = (__nv_bfloat16*)p1;   // pao
        for (int run = wid; run < 512; run += 12) {
            int a = run >> 7, ch = run & 127;
            const __nv_bfloat16* sp = ((a & 1) ? sl : sh) + ch*100;
            __nv_bfloat16* base = ((a < 2) ? eb : ob) + (a & 1)*(size_t)PTOT;
            __nv_bfloat16* dst = base + ((size_t)b*CC_ + ch)*PLANE
                               + (size_t)(y + 1)*WP + x0 + 1 + (a >> 1);
            if (a < 2) {
                if (lane == 0) dst[0]  = sp[1];
                if (lane == 1) dst[95] = sp[96];
                for (int j2 = lane; j2 < 47; j2 += 32) {
                    uint32_t v = *(const uint32_t*)(sp + 2 + 2*j2);
                    *(uint32_t*)(dst + 1 + 2*j2) = v;
                }
            } else {
                for (int j2 = lane; j2 < 48; j2 += 32) {
                    uint32_t lo2 = (uint32_t)*(const unsigned short*)(sp + 1 + 2*j2);
                    uint32_t hi2 = (uint32_t)*(const unsigned short*)(sp + 2 + 2*j2);
                    *(uint32_t*)(dst + 2*j2) = lo2 | (hi2 << 16);
                }
            }
        }
    } else {
        // stage: h/l planes in packed order [ch][cx*32+qx], then uint4 stores
        __syncthreads();
        __nv_bfloat16* sh = (__nv_bfloat16*)smem;      // 128*96
        __nv_bfloat16* sl = sh + 12288;
#pragma unroll
        for (int mh = 0; mh < 2; mh++) {
            int o = wm*32 + mh*16 + (lane >> 2);
#pragma unroll
            for (int j = 0; j < 4; j++) {
                int xb = wn*32 + j*8 + (lane & 3)*2;
#pragma unroll
                for (int t = 0; t < 4; t++) {
                    int oo = o + (t >> 1)*8;
                    int xx = xb + (t & 1);
                    int qx = xx / 3;
                    int cx = xx - qx*3;
                    float v = acc[mh][j][t];
                    __nv_bfloat16 h = __float2bfloat16(v);
                    int si = oo*96 + cx*32 + qx;
                    sh[si] = h;
                    sl[si] = __float2bfloat16(v - __bfloat162float(h));
                }
            }
        }
        __syncthreads();
        __nv_bfloat16* pp = (__nv_bfloat16*)p0;   // a1p/a2p (lo at +TOT)
        int cy = y % 3, qy = y / 3;
        int bx32 = blockIdx.x * 32;
#pragma unroll
        for (int i = 0; i < 8; i++) {
            int s = tid + i*NT;           // < 3072
            int seg = s >> 2, q = s & 3;
            int ch = seg / 6, r6 = seg - ch*6;
            int cx = r6 >> 1, hl = r6 & 1;
            const uint4* src = (const uint4*)((hl ? sl : sh) + ch*96 + cx*32 + q*8);
            __nv_bfloat16* dst = pp + hl*(size_t)TOT
                + (((size_t)b*CC_ + ch)*9 + cy*3 + cx)*4096 + qy*64 + bx32 + q*8;
            *(uint4*)dst = *src;
        }
    }
}

// ---------------- tensor-core attention correlation GEMM ----------------------
#define AT_STRIDE 80
#define AT_BYTES (128*AT_STRIDE)   // 10240
#define AT_STG (4*AT_BYTES)        // 40960
#define SMEM_ATTN (2*AT_STG)       // 81920

__global__ __launch_bounds__(256, 2) void attn_mma_kernel(
    const __nv_bfloat16* __restrict__ a1p, const __nv_bfloat16* __restrict__ a2p)
{
    extern __shared__ __align__(16) unsigned char smem[];
    const int ks  = blockIdx.x;
    const int cls = blockIdx.y;
    const int b   = blockIdx.z;
    const int tid = threadIdx.x;
    const int lane = tid & 31, wid = tid >> 5;
    const int wm = wid & 3, wn = wid >> 2;
    const uint32_t sb = smem_u32(smem);

    const size_t cbase = ((size_t)b*CC_*9 + cls)*4096 + ks*1024;
    const __nv_bfloat16* Ah_g = a2p + cbase;
    const __nv_bfloat16* Bh_g = a1p + cbase;

    int sdst[4];
    size_t ssrc[4];
    int shl[4];
#pragma unroll
    for (int i = 0; i < 4; i++) {
        int slot = tid + i*256;
        int r = (slot & 511) >> 2, q = slot & 3;
        shl[i]  = slot >> 9;
        sdst[i] = (slot >> 9)*AT_BYTES + r*AT_STRIDE + q*16;
        ssrc[i] = (size_t)r*36864 + q*8 + (size_t)(slot >> 9)*TOT;
    }

    float acc[2][8][4];
#pragma unroll
    for (int mh = 0; mh < 2; mh++)
#pragma unroll
        for (int nj = 0; nj < 8; nj++)
#pragma unroll
            for (int t = 0; t < 4; t++) acc[mh][nj][t] = 0.f;

    auto loadAB = [&](int c) {
        const uint32_t stg = sb + (c & 1)*AT_STG;
        const int kofs = c*32;
#pragma unroll
        for (int i = 0; i < 4; i++) {
            cp16(stg + sdst[i],               Ah_g + ssrc[i] + kofs);
            cp16(stg + 2*AT_BYTES + sdst[i],  Bh_g + ssrc[i] + kofs);
        }
        cp_commit();
    };

    loadAB(0);
    for (int c = 0; c < 32; c++) {
        cp_wait0();
        __syncthreads();
        if (c < 31) loadAB(c + 1);

        const uint32_t stg = sb + (c & 1)*AT_STG;
        const uint32_t Ah_s = stg;
        const uint32_t Al_s = stg + AT_BYTES;
        const uint32_t Bh_s = stg + 2*AT_BYTES;
        const uint32_t Bl_s = stg + 3*AT_BYTES;
#pragma unroll
        for (int st = 0; st < 2; st++) {
            unsigned Ah[2][4], Al[2][4];
#pragma unroll
            for (int mh = 0; mh < 2; mh++) {
                uint32_t off = (uint32_t)(wm*32 + mh*16 + (lane & 15))*AT_STRIDE
                             + ((lane >> 4) << 4) + st*32;
                ldsm4(Ah[mh], Ah_s + off);
                ldsm4(Al[mh], Al_s + off);
            }
#pragma unroll
            for (int ng = 0; ng < 4; ng++) {
                uint32_t off = (uint32_t)(wn*64 + ng*16 + (lane & 7)
                             + ((lane >> 3) & 1)*8)*AT_STRIDE
                             + st*32 + ((lane >> 4) & 1)*16;
                unsigned Bh[4], Bl[4];
                ldsm4(Bh, Bh_s + off);
                ldsm4(Bl, Bl_s + off);
#pragma unroll
                for (int mh = 0; mh < 2; mh++) {
#pragma unroll
                    for (int s2 = 0; s2 < 2; s2++) {
                        float* a = acc[mh][ng*2 + s2];
                        mma_bf16_2(a, Ah[mh], Bh[s2], Bh[s2 + 2]);
                        mma_bf16_2(a, Ah[mh], Bl[s2], Bl[s2 + 2]);
                        mma_bf16_2(a, Al[mh], Bh[s2], Bh[s2 + 2]);
                    }
                }
            }
        }
    }

#pragma unroll
    for (int mh = 0; mh < 2; mh++) {
        int o0 = wm*32 + mh*16 + (lane >> 2);
#pragma unroll
        for (int nj = 0; nj < 8; nj++) {
            int n0 = wn*64 + nj*8 + (lane & 3)*2;
            size_t r0 = ((size_t)b*CC_ + o0)*KK;
            size_t r1 = ((size_t)b*CC_ + o0 + 8)*KK;
            atomicAdd(&g_attn[r0 + (size_t)n0*9 + cls],       acc[mh][nj][0]);
            atomicAdd(&g_attn[r0 + (size_t)(n0 + 1)*9 + cls], acc[mh][nj][1]);
            atomicAdd(&g_attn[r1 + (size_t)n0*9 + cls],       acc[mh][nj][2]);
            atomicAdd(&g_attn[r1 + (size_t)(n0 + 1)*9 + cls], acc[mh][nj][3]);
        }
    }
}

// ---------------- softmax; emits dynamic kernels as bf16 hi/lo, permuted k ----
__global__ __launch_bounds__(256) void softmax_kernel() {
    __shared__ float red[256];
    const int row = blockIdx.x;
    const float* rp = g_attn + (size_t)row*KK;
    const float scale = 0.029462782549439483f;
    const int tid = threadIdx.x;

    float m = -1e30f;
    for (int e = tid; e < KK; e += 256) m = fmaxf(m, rp[e]);
    red[tid] = m; __syncthreads();
    for (int s = 128; s > 0; s >>= 1) {
        if (tid < s) red[tid] = fmaxf(red[tid], red[tid + s]);
        __syncthreads();
    }
    m = red[0] * scale;
    __syncthreads();

    float sum = 0.f;
    for (int e = tid; e < KK; e += 256) sum += expf(rp[e]*scale - m);
    red[tid] = sum; __syncthreads();
    for (int s = 128; s > 0; s >>= 1) {
        if (tid < s) red[tid] += red[tid + s];
        __syncthreads();
    }
    float inv = 1.f / red[0];

    for (int e = tid; e < KK; e += 256) {
        float p = expf(rp[e]*scale - m) * inv;
        int i = e / 9, rr = e - i*9;
        int knew = rr*128 + i;
        __nv_bfloat16 h = __float2bfloat16(p);
        g_k[(size_t)row*KK + knew] = h;
        g_k[(size_t)BB*CK + (size_t)row*KK + knew]
            = __float2bfloat16(p - __bfloat162float(h));
    }
}

// ---------------- BN stats over av partitioned by (group, parity) ------------
__global__ __launch_bounds__(256) void stats_kernel() {
    const int g = blockIdx.x;
    const int b = blockIdx.y;
    const int tid = threadIdx.x;
    float s00=0,s01=0,s10=0,s11=0,q00=0,q01=0,q10=0,q11=0;
    for (int c = 0; c < 4; c++) {
        const float* p = g_av + ((size_t)b*CC_ + g*4 + c)*HW;
        for (int e = tid; e < HW/2; e += 256) {
            int y = e / 96;
            int x2 = (e - y*96) * 2;
            float v0 = p[y*WW + x2];
            float v1 = p[y*WW + x2 + 1];
            if (y & 1) { s10 += v0; q10 += v0*v0; s11 += v1; q11 += v1*v1; }
            else       { s00 += v0; q00 += v0*v0; s01 += v1; q01 += v1*v1; }
        }
    }
    __shared__ float red[256];
    float vals[8] = {s00, s01, s10, s11, q00, q01, q10, q11};
#pragma unroll
    for (int v = 0; v < 8; v++) {
        red[tid] = vals[v]; __syncthreads();
        for (int st = 128; st > 0; st >>= 1) {
            if (tid < st) red[tid] += red[tid + st];
            __syncthreads();
        }
        if (tid == 0) {
            int p2 = v & 3;
            if (v < 4) atomicAdd(&g_sum[g*4 + p2],   red[0]);
            else       atomicAdd(&g_sumsq[g*4 + p2], red[0]);
        }
        __syncthreads();
    }
}

__global__ void finalize_kernel() {
    int c = threadIdx.x;
    if (c < CC_) {
        float n = (float)STAT_N;
        float mean = g_sum[c] / n;
        float var  = g_sumsq[c] / n - mean*mean;
        g_mean[c] = mean;
        g_inv[c]  = NORM_SCALE * rsqrtf(var + EPSV);
    }
}

// ---------------- fused stack-gather + BN + residual epilogue ----------------
__global__ __launch_bounds__(256) void output_kernel(const float* __restrict__ x,
                                                     const float* __restrict__ mom_p,
                                                     float* __restrict__ out) {
    const float mom = *mom_p;
    for (size_t idx = (size_t)blockIdx.x*blockDim.x + threadIdx.x; idx < (size_t)TOT;
         idx += (size_t)gridDim.x*blockDim.x) {
        size_t b = idx / CHW;
        int r  = (int)(idx - b*CHW);
        int c2 = r / HW;
        int rr = r - c2*HW;
        int Y = rr / WW, X = rr - Y*WW;
        int i2 = (Y >= 96), j2 = (X >= 96);
        int ph = Y - i2*96, pw = X - j2*96;
        int sc = (c2 & ~3) | (i2*2 + j2);
        int sy = ph*2 + ((c2 >> 1) & 1);
        int sx = pw*2 + (c2 & 1);
        float v = g_av[((size_t)b*CC_ + sc)*HW + (size_t)sy*WW + sx];
        out[idx] = mom * x[idx] + (v - g_mean[c2]) * g_inv[c2];
    }
}

// ---------------- launch -----------------------------------------------------
extern "C" void kernel_launch(void* const* d_in, const int* in_sizes, int n_in,
                              void* d_out, int out_size) {
    const float* x   = (const float*)d_in[0];
    const float* w1  = (const float*)d_in[1];
    const float* w2  = (const float*)d_in[2];
    const float* w3  = (const float*)d_in[3];
    const float* mom = (const float*)d_in[4];
    float* out = (float*)d_out;

    cudaFuncSetAttribute(conv_mma_kernel,
                         cudaFuncAttributeMaxDynamicSharedMemorySize, SMEM_CONV);
    cudaFuncSetAttribute(attn_mma_kernel,
                         cudaFuncAttributeMaxDynamicSharedMemorySize, SMEM_ATTN);

    __nv_bfloat16 *pxe, *pxo, *pae, *pao, *a1p, *a2p, *w, *k;
    float *av;
    cudaGetSymbolAddress((void**)&pxe, g_pxe);
    cudaGetSymbolAddress((void**)&pxo, g_pxo);
    cudaGetSymbolAddress((void**)&pae, g_pae);
    cudaGetSymbolAddress((void**)&pao, g_pao);
    cudaGetSymbolAddress((void**)&a1p, g_a1p);
    cudaGetSymbolAddress((void**)&a2p, g_a2p);
    cudaGetSymbolAddress((void**)&av,  g_av);
    cudaGetSymbolAddress((void**)&w,   g_w);
    cudaGetSymbolAddress((void**)&k,   g_k);

    zero_kernel<<<2048, 256>>>();
    split_x_pad_kernel<<<8192, 256>>>(x);
    split_w_kernel<<<dim3(144, 3), 256>>>(w1, w2, w3);

    dim3 cgrid(2, HH, BB);
    conv_mma_kernel<<<cgrid, NT, SMEM_CONV>>>(pxe, pxo,
        w + 0*(size_t)CK, 3*(long)CK, 0, a1p, nullptr, 2);
    conv_mma_kernel<<<cgrid, NT, SMEM_CONV>>>(pxe, pxo,
        w + 1*(size_t)CK, 3*(long)CK, 0, a2p, nullptr, 2);
    conv_mma_kernel<<<cgrid, NT, SMEM_CONV>>>(pxe, pxo,
        w + 2*(size_t)CK, 3*(long)CK, 0, pae, pao, 1);

    attn_mma_kernel<<<dim3(4, 9, BB), 256, SMEM_ATTN>>>(a1p, a2p);
    softmax_kernel<<<BB*CC_, 256>>>();

    conv_mma_kernel<<<cgrid, NT, SMEM_CONV>>>(pae, pao,
        k, (long)BB*CK, (long)CK, av, nullptr, 0);

    stats_kernel<<<dim3(32, 8), 256>>>();
    finalize_kernel<<<1, 128>>>();
    output_kernel<<<8192, 256>>>(x, mom, out);
}

// round 13
// speedup vs baseline: 1.0341x; 1.0138x over previous
#include <cuda_runtime.h>
#include <cuda_bf16.h>
#include <cstdint>

#define BB 8
#define CC_ 128
#define HH 192
#define WW 192
#define HW (HH*WW)
#define CHW (CC_*HW)
#define TOT (BB*CHW)
#define KK 1152            // C*9
#define EPSV 1e-5f
#define NORM_SCALE 0.1816f
#define STAT_N (BB*4*(HH/2)*(WW/2))   // 294912

// padded image geometry (1-px halo + alignment tail)
#define WP 200
#define HP 194
#define PLANE (HP*WP)          // 38800
#define PCHW (CC_*PLANE)
#define PTOT (BB*PCHW)

// ---------------- scratch (device globals; no allocations allowed) ------------
__device__ __align__(16) __nv_bfloat16 g_pxe_h[PTOT];
__device__ __align__(16) __nv_bfloat16 g_pxe_l[PTOT];
__device__ __align__(16) __nv_bfloat16 g_pxo_h[PTOT];
__device__ __align__(16) __nv_bfloat16 g_pxo_l[PTOT];
__device__ __align__(16) __nv_bfloat16 g_pae_h[PTOT];
__device__ __align__(16) __nv_bfloat16 g_pae_l[PTOT];
__device__ __align__(16) __nv_bfloat16 g_pao_h[PTOT];
__device__ __align__(16) __nv_bfloat16 g_pao_l[PTOT];
// parity-packed conv1/conv2 outputs: [b][ch][class(9)][4096]
__device__ __align__(16) __nv_bfloat16 g_a1p_h[TOT];
__device__ __align__(16) __nv_bfloat16 g_a1p_l[TOT];
__device__ __align__(16) __nv_bfloat16 g_a2p_h[TOT];
__device__ __align__(16) __nv_bfloat16 g_a2p_l[TOT];
__device__ float g_av[TOT];
__device__ __align__(16) __nv_bfloat16 g_wh[3*CC_*KK];    // [w][o][knew], knew=(r*3+dx)*128+ic
__device__ __align__(16) __nv_bfloat16 g_wl[3*CC_*KK];
__device__ __align__(16) __nv_bfloat16 g_kh[BB*CC_*KK];   // [b][o][knew]
__device__ __align__(16) __nv_bfloat16 g_kl[BB*CC_*KK];
__device__ float g_attn[BB*CC_*KK];        // [b][o][i*9+class]
__device__ float g_sum[CC_];
__device__ float g_sumsq[CC_];
__device__ float g_mean[CC_];
__device__ float g_inv[CC_];

// ---------------- PTX helpers -------------------------------------------------
__device__ __forceinline__ uint32_t smem_u32(const void* p) {
    uint32_t a;
    asm("{ .reg .u64 t; cvta.to.shared.u64 t, %1; cvt.u32.u64 %0, t; }"
        : "=r"(a) : "l"(p));
    return a;
}
__device__ __forceinline__ void ldsm4(unsigned* r, uint32_t addr) {
    asm volatile("ldmatrix.sync.aligned.m8n8.x4.shared.b16 {%0,%1,%2,%3}, [%4];"
                 : "=r"(r[0]), "=r"(r[1]), "=r"(r[2]), "=r"(r[3]) : "r"(addr));
}
__device__ __forceinline__ void ldsm4t(unsigned* r, uint32_t addr) {
    asm volatile("ldmatrix.sync.aligned.m8n8.x4.trans.shared.b16 {%0,%1,%2,%3}, [%4];"
                 : "=r"(r[0]), "=r"(r[1]), "=r"(r[2]), "=r"(r[3]) : "r"(addr));
}
__device__ __forceinline__ void mma_bf16(float* d, const unsigned* a, const unsigned* b) {
    asm volatile(
        "mma.sync.aligned.m16n8k16.row.col.f32.bf16.bf16.f32 "
        "{%0,%1,%2,%3}, {%4,%5,%6,%7}, {%8,%9}, {%0,%1,%2,%3};"
        : "+f"(d[0]), "+f"(d[1]), "+f"(d[2]), "+f"(d[3])
        : "r"(a[0]), "r"(a[1]), "r"(a[2]), "r"(a[3]), "r"(b[0]), "r"(b[1]));
}
__device__ __forceinline__ void mma_bf16_2(float* d, const unsigned* a,
                                           unsigned b0, unsigned b1) {
    asm volatile(
        "mma.sync.aligned.m16n8k16.row.col.f32.bf16.bf16.f32 "
        "{%0,%1,%2,%3}, {%4,%5,%6,%7}, {%8,%9}, {%0,%1,%2,%3};"
        : "+f"(d[0]), "+f"(d[1]), "+f"(d[2]), "+f"(d[3])
        : "r"(a[0]), "r"(a[1]), "r"(a[2]), "r"(a[3]), "r"(b0), "r"(b1));
}
__device__ __forceinline__ void cp16(uint32_t dst, const void* src) {
    asm volatile("cp.async.cg.shared.global [%0], [%1], 16;"
                 :: "r"(dst), "l"(src) : "memory");
}
__device__ __forceinline__ void cp4(uint32_t dst, const void* src) {
    asm volatile("cp.async.ca.shared.global [%0], [%1], 4;"
                 :: "r"(dst), "l"(src) : "memory");
}
__device__ __forceinline__ void cp_commit() {
    asm volatile("cp.async.commit_group;" ::: "memory");
}
__device__ __forceinline__ void cp_wait1() {
    asm volatile("cp.async.wait_group 1;" ::: "memory");
}
__device__ __forceinline__ void cp_wait0() {
    asm volatile("cp.async.wait_group 0;" ::: "memory");
}

// ---------------- zero accumulators + padded-array halos ----------------------
__global__ void zero_kernel() {
    int n = BB*CC_*KK;
    for (int i = blockIdx.x*blockDim.x + threadIdx.x; i < n; i += gridDim.x*blockDim.x)
        g_attn[i] = 0.f;
    const __nv_bfloat16 z = __float2bfloat16(0.f);
    int hn = BB*CC_*2128;
    for (int idx = blockIdx.x*blockDim.x + threadIdx.x; idx < hn;
         idx += gridDim.x*blockDim.x) {
        int plane = idx / 2128, e = idx - plane*2128;
        int row, px;
        if (e < 400) { row = (e < 200) ? 0 : 193; px = (e < 200) ? e : e - 200; }
        else { int e2 = e - 400; row = 1 + e2/9; int i9 = e2 - (e2/9)*9;
               px = (i9 < 2) ? i9 : 191 + i9; }
        size_t off = (size_t)plane*PLANE + row*WP + px;
        g_pae_h[off] = z; g_pae_l[off] = z; g_pao_h[off] = z; g_pao_l[off] = z;
    }
    if (blockIdx.x == 0 && threadIdx.x < CC_) {
        g_sum[threadIdx.x] = 0.f;
        g_sumsq[threadIdx.x] = 0.f;
    }
}

// ---------------- split x into padded bf16 hi/lo copies (aligned + shifted) ---
__global__ void split_x_pad_kernel(const float* __restrict__ x) {
    for (size_t idx = (size_t)blockIdx.x*blockDim.x + threadIdx.x; idx < (size_t)PTOT;
         idx += (size_t)gridDim.x*blockDim.x) {
        size_t bc = idx / PLANE;
        int p  = (int)(idx - bc*PLANE);
        int py = p / WP, px = p - py*WP;
        int yy = py - 1;
        float va = 0.f, vs = 0.f;
        if ((unsigned)yy < HH) {
            const float* row = x + bc*HW + (size_t)yy*WW;
            int xa = px - 1, xs = px - 2;
            if ((unsigned)xa < WW) va = row[xa];
            if ((unsigned)xs < WW) vs = row[xs];
        }
        __nv_bfloat16 ha = __float2bfloat16(va);
        g_pxe_h[idx] = ha;
        g_pxe_l[idx] = __float2bfloat16(va - __bfloat162float(ha));
        __nv_bfloat16 hs = __float2bfloat16(vs);
        g_pxo_h[idx] = hs;
        g_pxo_l[idx] = __float2bfloat16(vs - __bfloat162float(hs));
    }
}

// ---------------- split static weights (permuted k: knew=(r*3+dx)*128+ic) -----
__global__ void split_w_kernel(const float* __restrict__ w1,
                               const float* __restrict__ w2,
                               const float* __restrict__ w3) {
    const float* w = (blockIdx.y == 0) ? w1 : (blockIdx.y == 1) ? w2 : w3;
    int base = blockIdx.y * CC_ * KK;
    for (int e = blockIdx.x*blockDim.x + threadIdx.x; e < CC_*KK;
         e += gridDim.x*blockDim.x) {
        int o = e / KK, knew = e - o*KK;
        int rr = knew >> 7, ic = knew & 127;
        float v = w[(size_t)o*KK + ic*9 + rr];
        __nv_bfloat16 h = __float2bfloat16(v);
        g_wh[base + e] = h;
        g_wl[base + e] = __float2bfloat16(v - __bfloat162float(h));
    }
}

// ---------------- bf16 tensor-core implicit-GEMM 3x3 conv ---------------------
// CTA: M=128 o x N=96 px. K=1152 in 36 chunks of 32, (r,dx)-major.
// 3-stage cp.async pipeline. MMA inner loop is PRODUCT-MAJOR: all 12
// independent-acc MMAs of one product before the next product touches the
// same accumulators (reuse distance 1 -> 12).
#define A_STRIDE 80
#define B_STRIDE 208
#define A_BYTES (128*A_STRIDE)
#define B_BYTES (32*B_STRIDE)
#define STG (2*A_BYTES + 2*B_BYTES)
#define SMEM_CONV (3*STG)

__global__ __launch_bounds__(256, 2) void conv_mma_kernel(
    const __nv_bfloat16* __restrict__ pe_h, const __nv_bfloat16* __restrict__ pe_l,
    const __nv_bfloat16* __restrict__ po_h, const __nv_bfloat16* __restrict__ po_l,
    const __nv_bfloat16* __restrict__ wh_g, const __nv_bfloat16* __restrict__ wl_g,
    long wbstride, void* __restrict__ p0, void* __restrict__ p1,
    void* __restrict__ p2, void* __restrict__ p3, int mode)
{
    extern __shared__ __align__(16) unsigned char smem[];
    const int b  = blockIdx.z;
    const int y  = blockIdx.y;
    const int x0 = blockIdx.x * 96;
    const int tid = threadIdx.x;
    const int lane = tid & 31, wid = tid >> 5;
    const int wm = wid & 3, wn = wid >> 2;
    const uint32_t sb = smem_u32(smem);

    const __nv_bfloat16* peh = pe_h + (size_t)b*PCHW;
    const __nv_bfloat16* pel = pe_l + (size_t)b*PCHW;
    const __nv_bfloat16* poh = po_h + (size_t)b*PCHW;
    const __nv_bfloat16* pol = po_l + (size_t)b*PCHW;
    const __nv_bfloat16* wh = wh_g + (size_t)b*wbstride;
    const __nv_bfloat16* wl = wl_g + (size_t)b*wbstride;

    int bsrc[6], bdst[6];
#pragma unroll
    for (int i = 0; i < 6; i++) {
        int slot = tid + i*256;
        int rowt = slot / 48, np = slot - rowt*48;
        bsrc[i] = rowt*PLANE + np*2;
        bdst[i] = rowt*B_STRIDE + np*4;
    }
    int adst[4], aoff[4];
#pragma unroll
    for (int i = 0; i < 4; i++) {
        int slot = tid + i*256;
        int rem = slot & 511;
        int o = rem >> 2, qq = rem & 3;
        adst[i] = (slot >> 9)*A_BYTES + o*A_STRIDE + qq*16;
        aoff[i] = o*KK + qq*8;
    }

    float acc[2][6][4];
#pragma unroll
    for (int mh = 0; mh < 2; mh++)
#pragma unroll
        for (int j = 0; j < 6; j++)
#pragma unroll
            for (int t = 0; t < 4; t++) acc[mh][j][t] = 0.f;

    auto loadAB = [&](int c) {
        const uint32_t stg = sb + (c % 3)*STG;
        const int kofs = c*32;
#pragma unroll
        for (int i = 0; i < 2; i++) cp16(stg + adst[i], wh + aoff[i] + kofs);
#pragma unroll
        for (int i = 2; i < 4; i++) cp16(stg + adst[i], wl + aoff[i] + kofs);
        int r = c / 12, t = c - r*12;
        int dx = t >> 2, q = t & 3;
        int ibase = q*32*PLANE + (y + r)*WP + x0 + dx + (dx == 1);
        const __nv_bfloat16* hp = ((dx == 1) ? poh : peh) + ibase;
        const __nv_bfloat16* lp = ((dx == 1) ? pol : pel) + ibase;
        const uint32_t bb = stg + 2*A_BYTES;
#pragma unroll
        for (int i = 0; i < 6; i++) {
            cp4(bb + bdst[i],           hp + bsrc[i]);
            cp4(bb + B_BYTES + bdst[i], lp + bsrc[i]);
        }
        cp_commit();
    };

    loadAB(0);
    loadAB(1);

    for (int c = 0; c < 36; c++) {
        if (c < 34) cp_wait1(); else cp_wait0();
        __syncthreads();
        if (c < 34) loadAB(c + 2);

        const uint32_t stg = sb + (c % 3)*STG;
        const uint32_t Ah_s = stg;
        const uint32_t Al_s = stg + A_BYTES;
        const uint32_t Bh_s = stg + 2*A_BYTES;
        const uint32_t Bl_s = Bh_s + B_BYTES;
#pragma unroll
        for (int st = 0; st < 2; st++) {
            unsigned Ah[2][4], Al[2][4], Bh[3][4], Bl[3][4];
#pragma unroll
            for (int mh = 0; mh < 2; mh++) {
                uint32_t off = (uint32_t)(wm*32 + mh*16 + (lane & 15))*A_STRIDE
                             + ((lane >> 4) << 4) + st*32;
                ldsm4(Ah[mh], Ah_s + off);
                ldsm4(Al[mh], Al_s + off);
            }
#pragma unroll
            for (int nf = 0; nf < 3; nf++) {
                uint32_t off = (uint32_t)(st*16 + (lane & 15))*B_STRIDE
                             + wn*96 + nf*32 + ((lane >> 4) << 4);
                ldsm4t(Bh[nf], Bh_s + off);
                ldsm4t(Bl[nf], Bl_s + off);
            }
            // product-major: 12 independent accumulators between same-acc MMAs
#pragma unroll
            for (int mh = 0; mh < 2; mh++)
#pragma unroll
                for (int j = 0; j < 6; j++)
                    mma_bf16(acc[mh][j], Ah[mh], &Bh[j >> 1][(j & 1)*2]);
#pragma unroll
            for (int mh = 0; mh < 2; mh++)
#pragma unroll
                for (int j = 0; j < 6; j++)
                    mma_bf16(acc[mh][j], Ah[mh], &Bl[j >> 1][(j & 1)*2]);
#pragma unroll
            for (int mh = 0; mh < 2; mh++)
#pragma unroll
                for (int j = 0; j < 6; j++)
                    mma_bf16(acc[mh][j], Al[mh], &Bh[j >> 1][(j & 1)*2]);
        }
    }

    // ---- epilogue ----
    if (mode == 0) {
        float* out = (float*)p0;
#pragma unroll
        for (int mh = 0; mh < 2; mh++) {
            int o = wm*32 + mh*16 + (lane >> 2);
#pragma unroll
            for (int j = 0; j < 6; j++) {
                int x = x0 + wn*48 + j*8 + (lane & 3)*2;
                size_t i0 = ((size_t)b*CC_ + o)*HW + (size_t)y*WW + x;
                size_t i1 = i0 + (size_t)8*HW;
                *(float2*)(out + i0) = make_float2(acc[mh][j][0], acc[mh][j][1]);
                *(float2*)(out + i1) = make_float2(acc[mh][j][2], acc[mh][j][3]);
            }
        }
    } else if (mode == 1) {
        __syncthreads();
        __nv_bfloat16* sh = (__nv_bfloat16*)smem;      // 128*100
        __nv_bfloat16* sl = sh + 12800;
#pragma unroll
        for (int mh = 0; mh < 2; mh++) {
            int o = wm*32 + mh*16 + (lane >> 2);
#pragma unroll
            for (int j = 0; j < 6; j++) {
                int xb = wn*48 + j*8 + (lane & 3)*2;
#pragma unroll
                for (int t = 0; t < 4; t++) {
                    int oo = o + (t >> 1)*8;
                    int xx = xb + (t & 1);
                    float v = acc[mh][j][t];
                    __nv_bfloat16 h = __float2bfloat16(v);
                    int si = oo*100 + xx + 1;
                    sh[si] = h;
                    sl[si] = __float2bfloat16(v - __bfloat162float(h));
                }
            }
        }
        __syncthreads();
        __nv_bfloat16* eh  = (__nv_bfloat16*)p0;
        __nv_bfloat16* el  = (__nv_bfloat16*)p1;
        __nv_bfloat16* ohp = (__nv_bfloat16*)p2;
        __nv_bfloat16* olp = (__nv_bfloat16*)p3;
        for (int run = wid; run < 512; run += 8) {
            int a = run >> 7, ch = run & 127;
            const __nv_bfloat16* sp = ((a & 1) ? sl : sh) + ch*100;
            __nv_bfloat16* base = (a == 0) ? eh : (a == 1) ? el : (a == 2) ? ohp : olp;
            __nv_bfloat16* dst = base + ((size_t)b*CC_ + ch)*PLANE
                               + (size_t)(y + 1)*WP + x0 + 1 + (a >> 1);
            if (a < 2) {
                if (lane == 0) dst[0]  = sp[1];
                if (lane == 1) dst[95] = sp[96];
                for (int j2 = lane; j2 < 47; j2 += 32) {
                    uint32_t v = *(const uint32_t*)(sp + 2 + 2*j2);
                    *(uint32_t*)(dst + 1 + 2*j2) = v;
                }
            } else {
                for (int j2 = lane; j2 < 48; j2 += 32) {
                    uint32_t lo2 = (uint32_t)*(const unsigned short*)(sp + 1 + 2*j2);
                    uint32_t hi2 = (uint32_t)*(const unsigned short*)(sp + 2 + 2*j2);
                    *(uint32_t*)(dst + 2*j2) = lo2 | (hi2 << 16);
                }
            }
        }
    } else {
        __syncthreads();
        __nv_bfloat16* sh = (__nv_bfloat16*)smem;      // 128*96
        __nv_bfloat16* sl = sh + 12288;
#pragma unroll
        for (int mh = 0; mh < 2; mh++) {
            int o = wm*32 + mh*16 + (lane >> 2);
#pragma unroll
            for (int j = 0; j < 6; j++) {
                int xb = wn*48 + j*8 + (lane & 3)*2;
#pragma unroll
                for (int t = 0; t < 4; t++) {
                    int oo = o + (t >> 1)*8;
                    int xx = xb + (t & 1);
                    int qx = xx / 3;
                    int cx = xx - qx*3;
                    float v = acc[mh][j][t];
                    __nv_bfloat16 h = __float2bfloat16(v);
                    int si = oo*96 + cx*32 + qx;
                    sh[si] = h;
                    sl[si] = __float2bfloat16(v - __bfloat162float(h));
                }
            }
        }
        __syncthreads();
        __nv_bfloat16* ph = (__nv_bfloat16*)p0;
        __nv_bfloat16* pl = (__nv_bfloat16*)p1;
        int cy = y % 3, qy = y / 3;
        int bx32 = blockIdx.x * 32;
#pragma unroll
        for (int i = 0; i < 12; i++) {
            int s = tid + i*256;          // < 3072
            int seg = s >> 2, q = s & 3;
            int ch = seg / 6, r6 = seg - ch*6;
            int cx = r6 >> 1, hl = r6 & 1;
            const uint4* src = (const uint4*)((hl ? sl : sh) + ch*96 + cx*32 + q*8);
            __nv_bfloat16* dst = (hl ? pl : ph)
                + (((size_t)b*CC_ + ch)*9 + cy*3 + cx)*4096 + qy*64 + bx32 + q*8;
            *(uint4*)dst = *src;
        }
    }
}

// ---------------- tensor-core attention correlation GEMM ----------------------
#define AT_STRIDE 80
#define AT_BYTES (128*AT_STRIDE)   // 10240
#define AT_STG (4*AT_BYTES)        // 40960
#define SMEM_ATTN (2*AT_STG)       // 81920

__global__ __launch_bounds__(256, 2) void attn_mma_kernel(
    const __nv_bfloat16* __restrict__ a1h, const __nv_bfloat16* __restrict__ a1l,
    const __nv_bfloat16* __restrict__ a2h, const __nv_bfloat16* __restrict__ a2l)
{
    extern __shared__ __align__(16) unsigned char smem[];
    const int ks  = blockIdx.x;
    const int cls = blockIdx.y;
    const int b   = blockIdx.z;
    const int tid = threadIdx.x;
    const int lane = tid & 31, wid = tid >> 5;
    const int wm = wid & 3, wn = wid >> 2;
    const uint32_t sb = smem_u32(smem);

    const size_t cbase = ((size_t)b*CC_*9 + cls)*4096 + ks*1024;
    const __nv_bfloat16* Ah_g = a2h + cbase;
    const __nv_bfloat16* Al_g = a2l + cbase;
    const __nv_bfloat16* Bh_g = a1h + cbase;
    const __nv_bfloat16* Bl_g = a1l + cbase;

    int sdst[4];
    size_t ssrc[4];
#pragma unroll
    for (int i = 0; i < 4; i++) {
        int slot = tid + i*256;
        int r = (slot & 511) >> 2, q = slot & 3;
        sdst[i] = (slot >> 9)*AT_BYTES + r*AT_STRIDE + q*16;
        ssrc[i] = (size_t)r*36864 + q*8;
    }

    float acc[2][8][4];
#pragma unroll
    for (int mh = 0; mh < 2; mh++)
#pragma unroll
        for (int nj = 0; nj < 8; nj++)
#pragma unroll
            for (int t = 0; t < 4; t++) acc[mh][nj][t] = 0.f;

    auto loadAB = [&](int c) {
        const uint32_t stg = sb + (c & 1)*AT_STG;
        const int kofs = c*32;
#pragma unroll
        for (int i = 0; i < 2; i++) cp16(stg + sdst[i], Ah_g + ssrc[i] + kofs);
#pragma unroll
        for (int i = 2; i < 4; i++) cp16(stg + sdst[i], Al_g + ssrc[i] + kofs);
#pragma unroll
        for (int i = 0; i < 2; i++)
            cp16(stg + 2*AT_BYTES + sdst[i], Bh_g + ssrc[i] + kofs);
#pragma unroll
        for (int i = 2; i < 4; i++)
            cp16(stg + 2*AT_BYTES + sdst[i], Bl_g + ssrc[i] + kofs);
        cp_commit();
    };

    loadAB(0);
    for (int c = 0; c < 32; c++) {
        cp_wait0();
        __syncthreads();
        if (c < 31) loadAB(c + 1);

        const uint32_t stg = sb + (c & 1)*AT_STG;
        const uint32_t Ah_s = stg;
        const uint32_t Al_s = stg + AT_BYTES;
        const uint32_t Bh_s = stg + 2*AT_BYTES;
        const uint32_t Bl_s = stg + 3*AT_BYTES;
#pragma unroll
        for (int st = 0; st < 2; st++) {
            unsigned Ah[2][4], Al[2][4], Bh[4][4], Bl[4][4];
#pragma unroll
            for (int mh = 0; mh < 2; mh++) {
                uint32_t off = (uint32_t)(wm*32 + mh*16 + (lane & 15))*AT_STRIDE
                             + ((lane >> 4) << 4) + st*32;
                ldsm4(Ah[mh], Ah_s + off);
                ldsm4(Al[mh], Al_s + off);
            }
#pragma unroll
            for (int ng = 0; ng < 4; ng++) {
                uint32_t off = (uint32_t)(wn*64 + ng*16 + (lane & 7)
                             + ((lane >> 3) & 1)*8)*AT_STRIDE
                             + st*32 + ((lane >> 4) & 1)*16;
                ldsm4(Bh[ng], Bh_s + off);
                ldsm4(Bl[ng], Bl_s + off);
            }
            // product-major ordering (16 independent accs between reuses)
#pragma unroll
            for (int mh = 0; mh < 2; mh++)
#pragma unroll
                for (int ng = 0; ng < 4; ng++)
#pragma unroll
                    for (int s2 = 0; s2 < 2; s2++)
                        mma_bf16_2(acc[mh][ng*2 + s2], Ah[mh],
                                   Bh[ng][s2], Bh[ng][s2 + 2]);
#pragma unroll
            for (int mh = 0; mh < 2; mh++)
#pragma unroll
                for (int ng = 0; ng < 4; ng++)
#pragma unroll
                    for (int s2 = 0; s2 < 2; s2++)
                        mma_bf16_2(acc[mh][ng*2 + s2], Ah[mh],
                                   Bl[ng][s2], Bl[ng][s2 + 2]);
#pragma unroll
            for (int mh = 0; mh < 2; mh++)
#pragma unroll
                for (int ng = 0; ng < 4; ng++)
#pragma unroll
                    for (int s2 = 0; s2 < 2; s2++)
                        mma_bf16_2(acc[mh][ng*2 + s2], Al[mh],
                                   Bh[ng][s2], Bh[ng][s2 + 2]);
        }
    }

#pragma unroll
    for (int mh = 0; mh < 2; mh++) {
        int o0 = wm*32 + mh*16 + (lane >> 2);
#pragma unroll
        for (int nj = 0; nj < 8; nj++) {
            int n0 = wn*64 + nj*8 + (lane & 3)*2;
            size_t r0 = ((size_t)b*CC_ + o0)*KK;
            size_t r1 = ((size_t)b*CC_ + o0 + 8)*KK;
            atomicAdd(&g_attn[r0 + (size_t)n0*9 + cls],       acc[mh][nj][0]);
            atomicAdd(&g_attn[r0 + (size_t)(n0 + 1)*9 + cls], acc[mh][nj][1]);
            atomicAdd(&g_attn[r1 + (size_t)n0*9 + cls],       acc[mh][nj][2]);
            atomicAdd(&g_attn[r1 + (size_t)(n0 + 1)*9 + cls], acc[mh][nj][3]);
        }
    }
}

// ---------------- softmax; emits dynamic kernels as bf16 hi/lo, permuted k ----
__global__ __launch_bounds__(256) void softmax_kernel() {
    __shared__ float red[256];
    const int row = blockIdx.x;
    const float* rp = g_attn + (size_t)row*KK;
    const float scale = 0.029462782549439483f;
    const int tid = threadIdx.x;

    float m = -1e30f;
    for (int e = tid; e < KK; e += 256) m = fmaxf(m, rp[e]);
    red[tid] = m; __syncthreads();
    for (int s = 128; s > 0; s >>= 1) {
        if (tid < s) red[tid] = fmaxf(red[tid], red[tid + s]);
        __syncthreads();
    }
    m = red[0] * scale;
    __syncthreads();

    float sum = 0.f;
    for (int e = tid; e < KK; e += 256) sum += expf(rp[e]*scale - m);
    red[tid] = sum; __syncthreads();
    for (int s = 128; s > 0; s >>= 1) {
        if (tid < s) red[tid] += red[tid + s];
        __syncthreads();
    }
    float inv = 1.f / red[0];

    for (int e = tid; e < KK; e += 256) {
        float p = expf(rp[e]*scale - m) * inv;
        int i = e / 9, rr = e - i*9;
        int knew = rr*128 + i;
        __nv_bfloat16 h = __float2bfloat16(p);
        g_kh[(size_t)row*KK + knew] = h;
        g_kl[(size_t)row*KK + knew] = __float2bfloat16(p - __bfloat162float(h));
    }
}

// ---------------- BN stats over av partitioned by (group, parity) ------------
__global__ __launch_bounds__(256) void stats_kernel() {
    const int g = blockIdx.x;
    const int b = blockIdx.y;
    const int tid = threadIdx.x;
    float s00=0,s01=0,s10=0,s11=0,q00=0,q01=0,q10=0,q11=0;
    for (int c = 0; c < 4; c++) {
        const float* p = g_av + ((size_t)b*CC_ + g*4 + c)*HW;
        for (int e = tid; e < HW/2; e += 256) {
            int y = e / 96;
            int x2 = (e - y*96) * 2;
            float v0 = p[y*WW + x2];
            float v1 = p[y*WW + x2 + 1];
            if (y & 1) { s10 += v0; q10 += v0*v0; s11 += v1; q11 += v1*v1; }
            else       { s00 += v0; q00 += v0*v0; s01 += v1; q01 += v1*v1; }
        }
    }
    __shared__ float red[256];
    float vals[8] = {s00, s01, s10, s11, q00, q01, q10, q11};
#pragma unroll
    for (int v = 0; v < 8; v++) {
        red[tid] = vals[v]; __syncthreads();
        for (int st = 128; st > 0; st >>= 1) {
            if (tid < st) red[tid] += red[tid + st];
            __syncthreads();
        }
        if (tid == 0) {
            int p2 = v & 3;
            if (v < 4) atomicAdd(&g_sum[g*4 + p2],   red[0]);
            else       atomicAdd(&g_sumsq[g*4 + p2], red[0]);
        }
        __syncthreads();
    }
}

__global__ void finalize_kernel() {
    int c = threadIdx.x;
    if (c < CC_) {
        float n = (float)STAT_N;
        float mean = g_sum[c] / n;
        float var  = g_sumsq[c] / n - mean*mean;
        g_mean[c] = mean;
        g_inv[c]  = NORM_SCALE * rsqrtf(var + EPSV);
    }
}

// ---------------- fused stack-gather + BN + residual epilogue ----------------
__global__ __launch_bounds__(256) void output_kernel(const float* __restrict__ x,
                                                     const float* __restrict__ mom_p,
                                                     float* __restrict__ out) {
    const float mom = *mom_p;
    for (size_t idx = (size_t)blockIdx.x*blockDim.x + threadIdx.x; idx < (size_t)TOT;
         idx += (size_t)gridDim.x*blockDim.x) {
        size_t b = idx / CHW;
        int r  = (int)(idx - b*CHW);
        int c2 = r / HW;
        int rr = r - c2*HW;
        int Y = rr / WW, X = rr - Y*WW;
        int i2 = (Y >= 96), j2 = (X >= 96);
        int ph = Y - i2*96, pw = X - j2*96;
        int sc = (c2 & ~3) | (i2*2 + j2);
        int sy = ph*2 + ((c2 >> 1) & 1);
        int sx = pw*2 + (c2 & 1);
        float v = g_av[((size_t)b*CC_ + sc)*HW + (size_t)sy*WW + sx];
        out[idx] = mom * x[idx] + (v - g_mean[c2]) * g_inv[c2];
    }
}

// ---------------- launch -----------------------------------------------------
extern "C" void kernel_launch(void* const* d_in, const int* in_sizes, int n_in,
                              void* d_out, int out_size) {
    const float* x   = (const float*)d_in[0];
    const float* w1  = (const float*)d_in[1];
    const float* w2  = (const float*)d_in[2];
    const float* w3  = (const float*)d_in[3];
    const float* mom = (const float*)d_in[4];
    float* out = (float*)d_out;

    cudaFuncSetAttribute(conv_mma_kernel,
                         cudaFuncAttributeMaxDynamicSharedMemorySize, SMEM_CONV);
    cudaFuncSetAttribute(attn_mma_kernel,
                         cudaFuncAttributeMaxDynamicSharedMemorySize, SMEM_ATTN);

    __nv_bfloat16 *pxe_h, *pxe_l, *pxo_h, *pxo_l;
    __nv_bfloat16 *pae_h, *pae_l, *pao_h, *pao_l;
    __nv_bfloat16 *a1p_h, *a1p_l, *a2p_h, *a2p_l;
    __nv_bfloat16 *wh, *wl, *kh, *kl;
    float *av;
    cudaGetSymbolAddress((void**)&pxe_h, g_pxe_h);
    cudaGetSymbolAddress((void**)&pxe_l, g_pxe_l);
    cudaGetSymbolAddress((void**)&pxo_h, g_pxo_h);
    cudaGetSymbolAddress((void**)&pxo_l, g_pxo_l);
    cudaGetSymbolAddress((void**)&pae_h, g_pae_h);
    cudaGetSymbolAddress((void**)&pae_l, g_pae_l);
    cudaGetSymbolAddress((void**)&pao_h, g_pao_h);
    cudaGetSymbolAddress((void**)&pao_l, g_pao_l);
    cudaGetSymbolAddress((void**)&a1p_h, g_a1p_h);
    cudaGetSymbolAddress((void**)&a1p_l, g_a1p_l);
    cudaGetSymbolAddress((void**)&a2p_h, g_a2p_h);
    cudaGetSymbolAddress((void**)&a2p_l, g_a2p_l);
    cudaGetSymbolAddress((void**)&av,  g_av);
    cudaGetSymbolAddress((void**)&wh,  g_wh);
    cudaGetSymbolAddress((void**)&wl,  g_wl);
    cudaGetSymbolAddress((void**)&kh,  g_kh);
    cudaGetSymbolAddress((void**)&kl,  g_kl);

    zero_kernel<<<2048, 256>>>();
    split_x_pad_kernel<<<8192, 256>>>(x);
    split_w_kernel<<<dim3(144, 3), 256>>>(w1, w2, w3);

    dim3 cgrid(2, HH, BB);
    conv_mma_kernel<<<cgrid, 256, SMEM_CONV>>>(pxe_h, pxe_l, pxo_h, pxo_l,
        wh + 0*(size_t)CC_*KK, wl + 0*(size_t)CC_*KK, 0,
        a1p_h, a1p_l, nullptr, nullptr, 2);
    conv_mma_kernel<<<cgrid, 256, SMEM_CONV>>>(pxe_h, pxe_l, pxo_h, pxo_l,
        wh + 1*(size_t)CC_*KK, wl + 1*(size_t)CC_*KK, 0,
        a2p_h, a2p_l, nullptr, nullptr, 2);
    conv_mma_kernel<<<cgrid, 256, SMEM_CONV>>>(pxe_h, pxe_l, pxo_h, pxo_l,
        wh + 2*(size_t)CC_*KK, wl + 2*(size_t)CC_*KK, 0,
        pae_h, pae_l, pao_h, pao_l, 1);

    attn_mma_kernel<<<dim3(4, 9, BB), 256, SMEM_ATTN>>>(a1p_h, a1p_l, a2p_h, a2p_l);
    softmax_kernel<<<BB*CC_, 256>>>();

    conv_mma_kernel<<<cgrid, 256, SMEM_CONV>>>(pae_h, pae_l, pao_h, pao_l,
        kh, kl, (long)CC_*KK, av, nullptr, nullptr, nullptr, 0);

    stats_kernel<<<dim3(32, 8), 256>>>();
    finalize_kernel<<<1, 128>>>();
    output_kernel<<<8192, 256>>>(x, mom, out);
}

// round 14
// speedup vs baseline: 1.4185x; 1.3717x over previous
#include <cuda_runtime.h>
#include <cuda_fp16.h>
#include <cstdint>

#define BB 8
#define CC_ 128
#define HH 192
#define WW 192
#define HW (HH*WW)
#define CHW (CC_*HW)
#define TOT (BB*CHW)
#define KK 1152            // C*9
#define EPSV 1e-5f
#define NORM_SCALE 0.1816f
#define STAT_N (BB*4*(HH/2)*(WW/2))   // 294912

// padded image geometry (1-px halo + alignment tail)
#define WP 200
#define HP 194
#define PLANE (HP*WP)          // 38800
#define PCHW (CC_*PLANE)
#define PTOT (BB*PCHW)

// ---------------- scratch (device globals; no allocations allowed) ------------
__device__ __align__(16) __half g_pxe[PTOT];     // input hi, aligned shift (dx 0/2)
__device__ __align__(16) __half g_pxo[PTOT];     // input hi, odd shift (dx 1)
__device__ __align__(16) __half g_pae[PTOT];     // a3 hi, aligned
__device__ __align__(16) __half g_pao[PTOT];     // a3 hi, odd
// parity-packed conv outputs: [b][ch][class(9)][4096]
__device__ __align__(16) __half g_a1p[TOT];          // hi only (attn B)
__device__ __align__(16) __half g_a2p_h[TOT];        // attn A hi
__device__ __align__(16) __half g_a2p_l[TOT];        // attn A lo
__device__ float g_av[TOT];
__device__ __align__(16) __half g_wh[3*CC_*KK];  // [w][o][knew], knew=(r*3+dx)*128+ic
__device__ __align__(16) __half g_wl[3*CC_*KK];
__device__ __align__(16) __half g_kh[BB*CC_*KK]; // [b][o][knew]
__device__ __align__(16) __half g_kl[BB*CC_*KK];
__device__ float g_attn[BB*CC_*KK];        // [b][o][i*9+class]
__device__ float g_sum[CC_];
__device__ float g_sumsq[CC_];
__device__ float g_mean[CC_];
__device__ float g_inv[CC_];

// ---------------- PTX helpers -------------------------------------------------
__device__ __forceinline__ uint32_t smem_u32(const void* p) {
    uint32_t a;
    asm("{ .reg .u64 t; cvta.to.shared.u64 t, %1; cvt.u32.u64 %0, t; }"
        : "=r"(a) : "l"(p));
    return a;
}
__device__ __forceinline__ void ldsm4(unsigned* r, uint32_t addr) {
    asm volatile("ldmatrix.sync.aligned.m8n8.x4.shared.b16 {%0,%1,%2,%3}, [%4];"
                 : "=r"(r[0]), "=r"(r[1]), "=r"(r[2]), "=r"(r[3]) : "r"(addr));
}
__device__ __forceinline__ void ldsm4t(unsigned* r, uint32_t addr) {
    asm volatile("ldmatrix.sync.aligned.m8n8.x4.trans.shared.b16 {%0,%1,%2,%3}, [%4];"
                 : "=r"(r[0]), "=r"(r[1]), "=r"(r[2]), "=r"(r[3]) : "r"(addr));
}
__device__ __forceinline__ void mma_f16(float* d, const unsigned* a, const unsigned* b) {
    asm volatile(
        "mma.sync.aligned.m16n8k16.row.col.f32.f16.f16.f32 "
        "{%0,%1,%2,%3}, {%4,%5,%6,%7}, {%8,%9}, {%0,%1,%2,%3};"
        : "+f"(d[0]), "+f"(d[1]), "+f"(d[2]), "+f"(d[3])
        : "r"(a[0]), "r"(a[1]), "r"(a[2]), "r"(a[3]), "r"(b[0]), "r"(b[1]));
}
__device__ __forceinline__ void mma_f16_2(float* d, const unsigned* a,
                                          unsigned b0, unsigned b1) {
    asm volatile(
        "mma.sync.aligned.m16n8k16.row.col.f32.f16.f16.f32 "
        "{%0,%1,%2,%3}, {%4,%5,%6,%7}, {%8,%9}, {%0,%1,%2,%3};"
        : "+f"(d[0]), "+f"(d[1]), "+f"(d[2]), "+f"(d[3])
        : "r"(a[0]), "r"(a[1]), "r"(a[2]), "r"(a[3]), "r"(b0), "r"(b1));
}
__device__ __forceinline__ void cp16(uint32_t dst, const void* src) {
    asm volatile("cp.async.cg.shared.global [%0], [%1], 16;"
                 :: "r"(dst), "l"(src) : "memory");
}
__device__ __forceinline__ void cp4(uint32_t dst, const void* src) {
    asm volatile("cp.async.ca.shared.global [%0], [%1], 4;"
                 :: "r"(dst), "l"(src) : "memory");
}
__device__ __forceinline__ void cp_commit() {
    asm volatile("cp.async.commit_group;" ::: "memory");
}
__device__ __forceinline__ void cp_wait1() {
    asm volatile("cp.async.wait_group 1;" ::: "memory");
}
__device__ __forceinline__ void cp_wait0() {
    asm volatile("cp.async.wait_group 0;" ::: "memory");
}

// ---------------- zero accumulators + padded-array halos ----------------------
__global__ void zero_kernel() {
    int n = BB*CC_*KK;
    for (int i = blockIdx.x*blockDim.x + threadIdx.x; i < n; i += gridDim.x*blockDim.x)
        g_attn[i] = 0.f;
    const __half z = __float2half(0.f);
    int hn = BB*CC_*2128;
    for (int idx = blockIdx.x*blockDim.x + threadIdx.x; idx < hn;
         idx += gridDim.x*blockDim.x) {
        int plane = idx / 2128, e = idx - plane*2128;
        int row, px;
        if (e < 400) { row = (e < 200) ? 0 : 193; px = (e < 200) ? e : e - 200; }
        else { int e2 = e - 400; row = 1 + e2/9; int i9 = e2 - (e2/9)*9;
               px = (i9 < 2) ? i9 : 191 + i9; }
        size_t off = (size_t)plane*PLANE + row*WP + px;
        g_pae[off] = z; g_pao[off] = z;
    }
    if (blockIdx.x == 0 && threadIdx.x < CC_) {
        g_sum[threadIdx.x] = 0.f;
        g_sumsq[threadIdx.x] = 0.f;
    }
}

// ---------------- pad x into fp16 hi copies (aligned + shifted) ---------------
__global__ void split_x_pad_kernel(const float* __restrict__ x) {
    for (size_t idx = (size_t)blockIdx.x*blockDim.x + threadIdx.x; idx < (size_t)PTOT;
         idx += (size_t)gridDim.x*blockDim.x) {
        size_t bc = idx / PLANE;
        int p  = (int)(idx - bc*PLANE);
        int py = p / WP, px = p - py*WP;
        int yy = py - 1;
        float va = 0.f, vs = 0.f;
        if ((unsigned)yy < HH) {
            const float* row = x + bc*HW + (size_t)yy*WW;
            int xa = px - 1, xs = px - 2;
            if ((unsigned)xa < WW) va = row[xa];
            if ((unsigned)xs < WW) vs = row[xs];
        }
        g_pxe[idx] = __float2half(va);
        g_pxo[idx] = __float2half(vs);
    }
}

// ---------------- split static weights (permuted k: knew=(r*3+dx)*128+ic) -----
__global__ void split_w_kernel(const float* __restrict__ w1,
                               const float* __restrict__ w2,
                               const float* __restrict__ w3) {
    const float* w = (blockIdx.y == 0) ? w1 : (blockIdx.y == 1) ? w2 : w3;
    int base = blockIdx.y * CC_ * KK;
    for (int e = blockIdx.x*blockDim.x + threadIdx.x; e < CC_*KK;
         e += gridDim.x*blockDim.x) {
        int o = e / KK, knew = e - o*KK;
        int rr = knew >> 7, ic = knew & 127;
        float v = w[(size_t)o*KK + ic*9 + rr];
        __half h = __float2half(v);
        g_wh[base + e] = h;
        g_wl[base + e] = __float2half(v - __half2float(h));
    }
}

// ---------------- fp16 tensor-core implicit-GEMM 3x3 conv ---------------------
// CTA: M=128 o x N=96 px. K=1152 in 36 chunks of 32, (r,dx)-major.
// A = weights (hi+lo fp16), B = image (hi only). D = (Ah+Al)*Bh.
// 3-stage cp.async pipeline. Modes: 0 fp32 out; 1 padded hi planes (2 arrays);
// 2 parity-packed hi only; 3 parity-packed hi+lo.
#define A_STRIDE 80
#define B_STRIDE 208
#define A_BYTES (128*A_STRIDE)
#define B_BYTES (32*B_STRIDE)
#define STG (2*A_BYTES + B_BYTES)     // 27136
#define SMEM_CONV (3*STG)             // 81408

__global__ __launch_bounds__(256, 2) void conv_mma_kernel(
    const __half* __restrict__ pe, const __half* __restrict__ po,
    const __half* __restrict__ wh_g, const __half* __restrict__ wl_g,
    long wbstride, void* __restrict__ p0, void* __restrict__ p1, int mode)
{
    extern __shared__ __align__(16) unsigned char smem[];
    const int b  = blockIdx.z;
    const int y  = blockIdx.y;
    const int x0 = blockIdx.x * 96;
    const int tid = threadIdx.x;
    const int lane = tid & 31, wid = tid >> 5;
    const int wm = wid & 3, wn = wid >> 2;
    const uint32_t sb = smem_u32(smem);

    const __half* peb = pe + (size_t)b*PCHW;
    const __half* pob = po + (size_t)b*PCHW;
    const __half* wh = wh_g + (size_t)b*wbstride;
    const __half* wl = wl_g + (size_t)b*wbstride;

    int bsrc[6], bdst[6];
#pragma unroll
    for (int i = 0; i < 6; i++) {
        int slot = tid + i*256;              // < 1536
        int rowt = slot / 48, np = slot - rowt*48;
        bsrc[i] = rowt*PLANE + np*2;
        bdst[i] = rowt*B_STRIDE + np*4;
    }
    int adst[4], aoff[4];
#pragma unroll
    for (int i = 0; i < 4; i++) {
        int slot = tid + i*256;              // < 1024
        int rem = slot & 511;
        int o = rem >> 2, qq = rem & 3;
        adst[i] = (slot >> 9)*A_BYTES + o*A_STRIDE + qq*16;
        aoff[i] = o*KK + qq*8;
    }

    float acc[2][6][4];
#pragma unroll
    for (int mh = 0; mh < 2; mh++)
#pragma unroll
        for (int j = 0; j < 6; j++)
#pragma unroll
            for (int t = 0; t < 4; t++) acc[mh][j][t] = 0.f;

    auto loadAB = [&](int c) {
        const uint32_t stg = sb + (c % 3)*STG;
        const int kofs = c*32;
#pragma unroll
        for (int i = 0; i < 2; i++) cp16(stg + adst[i], wh + aoff[i] + kofs);
#pragma unroll
        for (int i = 2; i < 4; i++) cp16(stg + adst[i], wl + aoff[i] + kofs);
        int r = c / 12, t = c - r*12;
        int dx = t >> 2, q = t & 3;
        int ibase = q*32*PLANE + (y + r)*WP + x0 + dx + (dx == 1);
        const __half* hp = ((dx == 1) ? pob : peb) + ibase;
        const uint32_t bb = stg + 2*A_BYTES;
#pragma unroll
        for (int i = 0; i < 6; i++)
            cp4(bb + bdst[i], hp + bsrc[i]);
        cp_commit();
    };

    loadAB(0);
    loadAB(1);

    for (int c = 0; c < 36; c++) {
        if (c < 34) cp_wait1(); else cp_wait0();
        __syncthreads();
        if (c < 34) loadAB(c + 2);

        const uint32_t stg = sb + (c % 3)*STG;
        const uint32_t Ah_s = stg;
        const uint32_t Al_s = stg + A_BYTES;
        const uint32_t Bh_s = stg + 2*A_BYTES;
#pragma unroll
        for (int st = 0; st < 2; st++) {
            unsigned Ah[2][4], Al[2][4], Bh[3][4];
#pragma unroll
            for (int mh = 0; mh < 2; mh++) {
                uint32_t off = (uint32_t)(wm*32 + mh*16 + (lane & 15))*A_STRIDE
                             + ((lane >> 4) << 4) + st*32;
                ldsm4(Ah[mh], Ah_s + off);
                ldsm4(Al[mh], Al_s + off);
            }
#pragma unroll
            for (int nf = 0; nf < 3; nf++) {
                uint32_t off = (uint32_t)(st*16 + (lane & 15))*B_STRIDE
                             + wn*96 + nf*32 + ((lane >> 4) << 4);
                ldsm4t(Bh[nf], Bh_s + off);
            }
#pragma unroll
            for (int mh = 0; mh < 2; mh++)
#pragma unroll
                for (int j = 0; j < 6; j++)
                    mma_f16(acc[mh][j], Ah[mh], &Bh[j >> 1][(j & 1)*2]);
#pragma unroll
            for (int mh = 0; mh < 2; mh++)
#pragma unroll
                for (int j = 0; j < 6; j++)
                    mma_f16(acc[mh][j], Al[mh], &Bh[j >> 1][(j & 1)*2]);
        }
    }

    // ---- epilogue ----
    if (mode == 0) {
        float* out = (float*)p0;
#pragma unroll
        for (int mh = 0; mh < 2; mh++) {
            int o = wm*32 + mh*16 + (lane >> 2);
#pragma unroll
            for (int j = 0; j < 6; j++) {
                int x = x0 + wn*48 + j*8 + (lane & 3)*2;
                size_t i0 = ((size_t)b*CC_ + o)*HW + (size_t)y*WW + x;
                size_t i1 = i0 + (size_t)8*HW;
                *(float2*)(out + i0) = make_float2(acc[mh][j][0], acc[mh][j][1]);
                *(float2*)(out + i1) = make_float2(acc[mh][j][2], acc[mh][j][3]);
            }
        }
    } else if (mode == 1) {
        // stage hi plane, stride 100 per ch, +1 element shift
        __syncthreads();
        __half* sh = (__half*)smem;      // 128*100
#pragma unroll
        for (int mh = 0; mh < 2; mh++) {
            int o = wm*32 + mh*16 + (lane >> 2);
#pragma unroll
            for (int j = 0; j < 6; j++) {
                int xb = wn*48 + j*8 + (lane & 3)*2;
#pragma unroll
                for (int t = 0; t < 4; t++) {
                    int oo = o + (t >> 1)*8;
                    int xx = xb + (t & 1);
                    sh[oo*100 + xx + 1] = __float2half(acc[mh][j][t]);
                }
            }
        }
        __syncthreads();
        __half* eh = (__half*)p0;   // pae
        __half* oh = (__half*)p1;   // pao
        for (int run = wid; run < 256; run += 8) {
            int a = run >> 7, ch = run & 127;
            const __half* sp = sh + ch*100;
            __half* base = (a == 0) ? eh : oh;
            __half* dst = base + ((size_t)b*CC_ + ch)*PLANE
                        + (size_t)(y + 1)*WP + x0 + 1 + a;
            if (a == 0) {
                if (lane == 0) dst[0]  = sp[1];
                if (lane == 1) dst[95] = sp[96];
                for (int j2 = lane; j2 < 47; j2 += 32) {
                    uint32_t v = *(const uint32_t*)(sp + 2 + 2*j2);
                    *(uint32_t*)(dst + 1 + 2*j2) = v;
                }
            } else {
                for (int j2 = lane; j2 < 48; j2 += 32) {
                    uint32_t lo2 = (uint32_t)*(const unsigned short*)(sp + 1 + 2*j2);
                    uint32_t hi2 = (uint32_t)*(const unsigned short*)(sp + 2 + 2*j2);
                    *(uint32_t*)(dst + 2*j2) = lo2 | (hi2 << 16);
                }
            }
        }
    } else {
        // parity-packed: stage [ch][cx*32+qx] planes, then uint4 stores
        __syncthreads();
        __half* sh = (__half*)smem;      // 128*96
        __half* sl = sh + 12288;
        const bool wantlo = (mode == 3);
#pragma unroll
        for (int mh = 0; mh < 2; mh++) {
            int o = wm*32 + mh*16 + (lane >> 2);
#pragma unroll
            for (int j = 0; j < 6; j++) {
                int xb = wn*48 + j*8 + (lane & 3)*2;
#pragma unroll
                for (int t = 0; t < 4; t++) {
                    int oo = o + (t >> 1)*8;
                    int xx = xb + (t & 1);
                    int qx = xx / 3;
                    int cx = xx - qx*3;
                    float v = acc[mh][j][t];
                    __half h = __float2half(v);
                    int si = oo*96 + cx*32 + qx;
                    sh[si] = h;
                    if (wantlo) sl[si] = __float2half(v - __half2float(h));
                }
            }
        }
        __syncthreads();
        __half* ph = (__half*)p0;
        __half* pl = (__half*)p1;
        int cy = y % 3, qy = y / 3;
        int bx32 = blockIdx.x * 32;
        if (mode == 2) {
#pragma unroll
            for (int i = 0; i < 6; i++) {
                int s = tid + i*256;      // < 1536
                int seg = s >> 2, q = s & 3;
                int ch = seg / 3, cx = seg - ch*3;
                const uint4* src = (const uint4*)(sh + ch*96 + cx*32 + q*8);
                __half* dst = ph
                    + (((size_t)b*CC_ + ch)*9 + cy*3 + cx)*4096 + qy*64 + bx32 + q*8;
                *(uint4*)dst = *src;
            }
        } else {
#pragma unroll
            for (int i = 0; i < 12; i++) {
                int s = tid + i*256;      // < 3072
                int seg = s >> 2, q = s & 3;
                int ch = seg / 6, r6 = seg - ch*6;
                int cx = r6 >> 1, hl = r6 & 1;
                const uint4* src = (const uint4*)((hl ? sl : sh) + ch*96 + cx*32 + q*8);
                __half* dst = (hl ? pl : ph)
                    + (((size_t)b*CC_ + ch)*9 + cy*3 + cx)*4096 + qy*64 + bx32 + q*8;
                *(uint4*)dst = *src;
            }
        }
    }
}

// ---------------- tensor-core attention correlation GEMM ----------------------
// A = a2 (hi+lo), B = a1 (hi only). M=128(o) x N=128(i), K slab 1024.
#define AT_STRIDE 80
#define AT_BYTES (128*AT_STRIDE)   // 10240
#define AT_STG (3*AT_BYTES)        // 30720
#define SMEM_ATTN (2*AT_STG)       // 61440

__global__ __launch_bounds__(256, 2) void attn_mma_kernel(
    const __half* __restrict__ a1h,
    const __half* __restrict__ a2h, const __half* __restrict__ a2l)
{
    extern __shared__ __align__(16) unsigned char smem[];
    const int ks  = blockIdx.x;
    const int cls = blockIdx.y;
    const int b   = blockIdx.z;
    const int tid = threadIdx.x;
    const int lane = tid & 31, wid = tid >> 5;
    const int wm = wid & 3, wn = wid >> 2;
    const uint32_t sb = smem_u32(smem);

    const size_t cbase = ((size_t)b*CC_*9 + cls)*4096 + ks*1024;
    const __half* Ah_g = a2h + cbase;
    const __half* Al_g = a2l + cbase;
    const __half* Bh_g = a1h + cbase;

    int sdst[4];
    size_t ssrc[4];
#pragma unroll
    for (int i = 0; i < 4; i++) {
        int slot = tid + i*256;
        int r = (slot & 511) >> 2, q = slot & 3;
        sdst[i] = (slot >> 9)*AT_BYTES + r*AT_STRIDE + q*16;
        ssrc[i] = (size_t)r*36864 + q*8;
    }

    float acc[2][8][4];
#pragma unroll
    for (int mh = 0; mh < 2; mh++)
#pragma unroll
        for (int nj = 0; nj < 8; nj++)
#pragma unroll
            for (int t = 0; t < 4; t++) acc[mh][nj][t] = 0.f;

    auto loadAB = [&](int c) {
        const uint32_t stg = sb + (c & 1)*AT_STG;
        const int kofs = c*32;
#pragma unroll
        for (int i = 0; i < 2; i++) cp16(stg + sdst[i], Ah_g + ssrc[i] + kofs);
#pragma unroll
        for (int i = 2; i < 4; i++) cp16(stg + sdst[i], Al_g + ssrc[i] + kofs);
#pragma unroll
        for (int i = 0; i < 2; i++)
            cp16(stg + 2*AT_BYTES + sdst[i], Bh_g + ssrc[i] + kofs);
        cp_commit();
    };

    loadAB(0);
    for (int c = 0; c < 32; c++) {
        cp_wait0();
        __syncthreads();
        if (c < 31) loadAB(c + 1);

        const uint32_t stg = sb + (c & 1)*AT_STG;
        const uint32_t Ah_s = stg;
        const uint32_t Al_s = stg + AT_BYTES;
        const uint32_t Bh_s = stg + 2*AT_BYTES;
#pragma unroll
        for (int st = 0; st < 2; st++) {
            unsigned Ah[2][4], Al[2][4], Bh[4][4];
#pragma unroll
            for (int mh = 0; mh < 2; mh++) {
                uint32_t off = (uint32_t)(wm*32 + mh*16 + (lane & 15))*AT_STRIDE
                             + ((lane >> 4) << 4) + st*32;
                ldsm4(Ah[mh], Ah_s + off);
                ldsm4(Al[mh], Al_s + off);
            }
#pragma unroll
            for (int ng = 0; ng < 4; ng++) {
                uint32_t off = (uint32_t)(wn*64 + ng*16 + (lane & 7)
                             + ((lane >> 3) & 1)*8)*AT_STRIDE
                             + st*32 + ((lane >> 4) & 1)*16;
                ldsm4(Bh[ng], Bh_s + off);
            }
#pragma unroll
            for (int mh = 0; mh < 2; mh++)
#pragma unroll
                for (int ng = 0; ng < 4; ng++)
#pragma unroll
                    for (int s2 = 0; s2 < 2; s2++)
                        mma_f16_2(acc[mh][ng*2 + s2], Ah[mh],
                                  Bh[ng][s2], Bh[ng][s2 + 2]);
#pragma unroll
            for (int mh = 0; mh < 2; mh++)
#pragma unroll
                for (int ng = 0; ng < 4; ng++)
#pragma unroll
                    for (int s2 = 0; s2 < 2; s2++)
                        mma_f16_2(acc[mh][ng*2 + s2], Al[mh],
                                  Bh[ng][s2], Bh[ng][s2 + 2]);
        }
    }

#pragma unroll
    for (int mh = 0; mh < 2; mh++) {
        int o0 = wm*32 + mh*16 + (lane >> 2);
#pragma unroll
        for (int nj = 0; nj < 8; nj++) {
            int n0 = wn*64 + nj*8 + (lane & 3)*2;
            size_t r0 = ((size_t)b*CC_ + o0)*KK;
            size_t r1 = ((size_t)b*CC_ + o0 + 8)*KK;
            atomicAdd(&g_attn[r0 + (size_t)n0*9 + cls],       acc[mh][nj][0]);
            atomicAdd(&g_attn[r0 + (size_t)(n0 + 1)*9 + cls], acc[mh][nj][1]);
            atomicAdd(&g_attn[r1 + (size_t)n0*9 + cls],       acc[mh][nj][2]);
            atomicAdd(&g_attn[r1 + (size_t)(n0 + 1)*9 + cls], acc[mh][nj][3]);
        }
    }
}

// ---------------- softmax; emits dynamic kernels as fp16 hi/lo, permuted k ----
__global__ __launch_bounds__(256) void softmax_kernel() {
    __shared__ float red[256];
    const int row = blockIdx.x;
    const float* rp = g_attn + (size_t)row*KK;
    const float scale = 0.029462782549439483f;
    const int tid = threadIdx.x;

    float m = -1e30f;
    for (int e = tid; e < KK; e += 256) m = fmaxf(m, rp[e]);
    red[tid] = m; __syncthreads();
    for (int s = 128; s > 0; s >>= 1) {
        if (tid < s) red[tid] = fmaxf(red[tid], red[tid + s]);
        __syncthreads();
    }
    m = red[0] * scale;
    __syncthreads();

    float sum = 0.f;
    for (int e = tid; e < KK; e += 256) sum += expf(rp[e]*scale - m);
    red[tid] = sum; __syncthreads();
    for (int s = 128; s > 0; s >>= 1) {
        if (tid < s) red[tid] += red[tid + s];
        __syncthreads();
    }
    float inv = 1.f / red[0];

    for (int e = tid; e < KK; e += 256) {
        float p = expf(rp[e]*scale - m) * inv;
        int i = e / 9, rr = e - i*9;
        int knew = rr*128 + i;
        __half h = __float2half(p);
        g_kh[(size_t)row*KK + knew] = h;
        g_kl[(size_t)row*KK + knew] = __float2half(p - __half2float(h));
    }
}

// ---------------- BN stats over av partitioned by (group, parity) ------------
__global__ __launch_bounds__(256) void stats_kernel() {
    const int g = blockIdx.x;
    const int b = blockIdx.y;
    const int tid = threadIdx.x;
    float s00=0,s01=0,s10=0,s11=0,q00=0,q01=0,q10=0,q11=0;
    for (int c = 0; c < 4; c++) {
        const float* p = g_av + ((size_t)b*CC_ + g*4 + c)*HW;
        for (int e = tid; e < HW/2; e += 256) {
            int y = e / 96;
            int x2 = (e - y*96) * 2;
            float v0 = p[y*WW + x2];
            float v1 = p[y*WW + x2 + 1];
            if (y & 1) { s10 += v0; q10 += v0*v0; s11 += v1; q11 += v1*v1; }
            else       { s00 += v0; q00 += v0*v0; s01 += v1; q01 += v1*v1; }
        }
    }
    __shared__ float red[256];
    float vals[8] = {s00, s01, s10, s11, q00, q01, q10, q11};
#pragma unroll
    for (int v = 0; v < 8; v++) {
        red[tid] = vals[v]; __syncthreads();
        for (int st = 128; st > 0; st >>= 1) {
            if (tid < st) red[tid] += red[tid + st];
            __syncthreads();
        }
        if (tid == 0) {
            int p2 = v & 3;
            if (v < 4) atomicAdd(&g_sum[g*4 + p2],   red[0]);
            else       atomicAdd(&g_sumsq[g*4 + p2], red[0]);
        }
        __syncthreads();
    }
}

__global__ void finalize_kernel() {
    int c = threadIdx.x;
    if (c < CC_) {
        float n = (float)STAT_N;
        float mean = g_sum[c] / n;
        float var  = g_sumsq[c] / n - mean*mean;
        g_mean[c] = mean;
        g_inv[c]  = NORM_SCALE * rsqrtf(var + EPSV);
    }
}

// ---------------- fused stack-gather + BN + residual epilogue ----------------
__global__ __launch_bounds__(256) void output_kernel(const float* __restrict__ x,
                                                     const float* __restrict__ mom_p,
                                                     float* __restrict__ out) {
    const float mom = *mom_p;
    for (size_t idx = (size_t)blockIdx.x*blockDim.x + threadIdx.x; idx < (size_t)TOT;
         idx += (size_t)gridDim.x*blockDim.x) {
        size_t b = idx / CHW;
        int r  = (int)(idx - b*CHW);
        int c2 = r / HW;
        int rr = r - c2*HW;
        int Y = rr / WW, X = rr - Y*WW;
        int i2 = (Y >= 96), j2 = (X >= 96);
        int ph = Y - i2*96, pw = X - j2*96;
        int sc = (c2 & ~3) | (i2*2 + j2);
        int sy = ph*2 + ((c2 >> 1) & 1);
        int sx = pw*2 + (c2 & 1);
        float v = g_av[((size_t)b*CC_ + sc)*HW + (size_t)sy*WW + sx];
        out[idx] = mom * x[idx] + (v - g_mean[c2]) * g_inv[c2];
    }
}

// ---------------- launch -----------------------------------------------------
extern "C" void kernel_launch(void* const* d_in, const int* in_sizes, int n_in,
                              void* d_out, int out_size) {
    const float* x   = (const float*)d_in[0];
    const float* w1  = (const float*)d_in[1];
    const float* w2  = (const float*)d_in[2];
    const float* w3  = (const float*)d_in[3];
    const float* mom = (const float*)d_in[4];
    float* out = (float*)d_out;

    cudaFuncSetAttribute(conv_mma_kernel,
                         cudaFuncAttributeMaxDynamicSharedMemorySize, SMEM_CONV);
    cudaFuncSetAttribute(attn_mma_kernel,
                         cudaFuncAttributeMaxDynamicSharedMemorySize, SMEM_ATTN);

    __half *pxe, *pxo, *pae, *pao, *a1p, *a2p_h, *a2p_l, *wh, *wl, *kh, *kl;
    float *av;
    cudaGetSymbolAddress((void**)&pxe,   g_pxe);
    cudaGetSymbolAddress((void**)&pxo,   g_pxo);
    cudaGetSymbolAddress((void**)&pae,   g_pae);
    cudaGetSymbolAddress((void**)&pao,   g_pao);
    cudaGetSymbolAddress((void**)&a1p,   g_a1p);
    cudaGetSymbolAddress((void**)&a2p_h, g_a2p_h);
    cudaGetSymbolAddress((void**)&a2p_l, g_a2p_l);
    cudaGetSymbolAddress((void**)&av,    g_av);
    cudaGetSymbolAddress((void**)&wh,    g_wh);
    cudaGetSymbolAddress((void**)&wl,    g_wl);
    cudaGetSymbolAddress((void**)&kh,    g_kh);
    cudaGetSymbolAddress((void**)&kl,    g_kl);

    zero_kernel<<<2048, 256>>>();
    split_x_pad_kernel<<<8192, 256>>>(x);
    split_w_kernel<<<dim3(144, 3), 256>>>(w1, w2, w3);

    dim3 cgrid(2, HH, BB);
    conv_mma_kernel<<<cgrid, 256, SMEM_CONV>>>(pxe, pxo,
        wh + 0*(size_t)CC_*KK, wl + 0*(size_t)CC_*KK, 0, a1p, nullptr, 2);
    conv_mma_kernel<<<cgrid, 256, SMEM_CONV>>>(pxe, pxo,
        wh + 1*(size_t)CC_*KK, wl + 1*(size_t)CC_*KK, 0, a2p_h, a2p_l, 3);
    conv_mma_kernel<<<cgrid, 256, SMEM_CONV>>>(pxe, pxo,
        wh + 2*(size_t)CC_*KK, wl + 2*(size_t)CC_*KK, 0, pae, pao, 1);

    attn_mma_kernel<<<dim3(4, 9, BB), 256, SMEM_ATTN>>>(a1p, a2p_h, a2p_l);
    softmax_kernel<<<BB*CC_, 256>>>();

    conv_mma_kernel<<<cgrid, 256, SMEM_CONV>>>(pae, pao,
        kh, kl, (long)CC_*KK, av, nullptr, 0);

    stats_kernel<<<dim3(32, 8), 256>>>();
    finalize_kernel<<<1, 128>>>();
    output_kernel<<<8192, 256>>>(x, mom, out);
}

// round 15
// speedup vs baseline: 2.0969x; 1.4782x over previous
#include <cuda_runtime.h>
#include <cuda_fp16.h>
#include <cstdint>

#define BB 8
#define CC_ 128
#define HH 192
#define WW 192
#define HW (HH*WW)
#define CHW (CC_*HW)
#define TOT (BB*CHW)
#define KK 1152            // C*9
#define EPSV 1e-5f
#define NORM_SCALE 0.1816f
#define STAT_N (BB*4*(HH/2)*(WW/2))   // 294912

// padded image geometry (1-px halo + alignment tail)
#define WP 200
#define HP 194
#define PLANE (HP*WP)          // 38800
#define PCHW (CC_*PLANE)
#define PTOT (BB*PCHW)

// ---------------- scratch (device globals; no allocations allowed) ------------
__device__ __align__(16) __half g_pxe[PTOT];     // input, aligned shift (dx 0/2)
__device__ __align__(16) __half g_pxo[PTOT];     // input, odd shift (dx 1)
__device__ __align__(16) __half g_pae[PTOT];     // a3, aligned
__device__ __align__(16) __half g_pao[PTOT];     // a3, odd
// parity-packed conv outputs: [b][ch][class(9)][4096]
__device__ __align__(16) __half g_a1p[TOT];
__device__ __align__(16) __half g_a2p[TOT];
__device__ float g_av[TOT];
__device__ __align__(16) __half g_w[3*CC_*KK];   // [w][o][knew], knew=(r*3+dx)*128+ic
__device__ __align__(16) __half g_k[BB*CC_*KK];  // [b][o][knew]
__device__ float g_attn[BB*CC_*KK];        // [b][o][i*9+class]
__device__ float g_sum[CC_];
__device__ float g_sumsq[CC_];
__device__ float g_mean[CC_];
__device__ float g_inv[CC_];

// ---------------- PTX helpers -------------------------------------------------
__device__ __forceinline__ uint32_t smem_u32(const void* p) {
    uint32_t a;
    asm("{ .reg .u64 t; cvta.to.shared.u64 t, %1; cvt.u32.u64 %0, t; }"
        : "=r"(a) : "l"(p));
    return a;
}
__device__ __forceinline__ void ldsm4(unsigned* r, uint32_t addr) {
    asm volatile("ldmatrix.sync.aligned.m8n8.x4.shared.b16 {%0,%1,%2,%3}, [%4];"
                 : "=r"(r[0]), "=r"(r[1]), "=r"(r[2]), "=r"(r[3]) : "r"(addr));
}
__device__ __forceinline__ void ldsm4t(unsigned* r, uint32_t addr) {
    asm volatile("ldmatrix.sync.aligned.m8n8.x4.trans.shared.b16 {%0,%1,%2,%3}, [%4];"
                 : "=r"(r[0]), "=r"(r[1]), "=r"(r[2]), "=r"(r[3]) : "r"(addr));
}
__device__ __forceinline__ void mma_f16(float* d, const unsigned* a, const unsigned* b) {
    asm volatile(
        "mma.sync.aligned.m16n8k16.row.col.f32.f16.f16.f32 "
        "{%0,%1,%2,%3}, {%4,%5,%6,%7}, {%8,%9}, {%0,%1,%2,%3};"
        : "+f"(d[0]), "+f"(d[1]), "+f"(d[2]), "+f"(d[3])
        : "r"(a[0]), "r"(a[1]), "r"(a[2]), "r"(a[3]), "r"(b[0]), "r"(b[1]));
}
__device__ __forceinline__ void mma_f16_2(float* d, const unsigned* a,
                                          unsigned b0, unsigned b1) {
    asm volatile(
        "mma.sync.aligned.m16n8k16.row.col.f32.f16.f16.f32 "
        "{%0,%1,%2,%3}, {%4,%5,%6,%7}, {%8,%9}, {%0,%1,%2,%3};"
        : "+f"(d[0]), "+f"(d[1]), "+f"(d[2]), "+f"(d[3])
        : "r"(a[0]), "r"(a[1]), "r"(a[2]), "r"(a[3]), "r"(b0), "r"(b1));
}
__device__ __forceinline__ void cp16(uint32_t dst, const void* src) {
    asm volatile("cp.async.cg.shared.global [%0], [%1], 16;"
                 :: "r"(dst), "l"(src) : "memory");
}
__device__ __forceinline__ void cp4(uint32_t dst, const void* src) {
    asm volatile("cp.async.ca.shared.global [%0], [%1], 4;"
                 :: "r"(dst), "l"(src) : "memory");
}
__device__ __forceinline__ void cp_commit() {
    asm volatile("cp.async.commit_group;" ::: "memory");
}
__device__ __forceinline__ void cp_wait1() {
    asm volatile("cp.async.wait_group 1;" ::: "memory");
}
__device__ __forceinline__ void cp_wait0() {
    asm volatile("cp.async.wait_group 0;" ::: "memory");
}

// ---------------- zero accumulators + padded-array halos ----------------------
__global__ void zero_kernel() {
    int n = BB*CC_*KK;
    for (int i = blockIdx.x*blockDim.x + threadIdx.x; i < n; i += gridDim.x*blockDim.x)
        g_attn[i] = 0.f;
    const __half z = __float2half(0.f);
    int hn = BB*CC_*2128;
    for (int idx = blockIdx.x*blockDim.x + threadIdx.x; idx < hn;
         idx += gridDim.x*blockDim.x) {
        int plane = idx / 2128, e = idx - plane*2128;
        int row, px;
        if (e < 400) { row = (e < 200) ? 0 : 193; px = (e < 200) ? e : e - 200; }
        else { int e2 = e - 400; row = 1 + e2/9; int i9 = e2 - (e2/9)*9;
               px = (i9 < 2) ? i9 : 191 + i9; }
        size_t off = (size_t)plane*PLANE + row*WP + px;
        g_pae[off] = z; g_pao[off] = z;
    }
    if (blockIdx.x == 0 && threadIdx.x < CC_) {
        g_sum[threadIdx.x] = 0.f;
        g_sumsq[threadIdx.x] = 0.f;
    }
}

// ---------------- pad x into fp16 copies (aligned + shifted) ------------------
__global__ void split_x_pad_kernel(const float* __restrict__ x) {
    for (size_t idx = (size_t)blockIdx.x*blockDim.x + threadIdx.x; idx < (size_t)PTOT;
         idx += (size_t)gridDim.x*blockDim.x) {
        size_t bc = idx / PLANE;
        int p  = (int)(idx - bc*PLANE);
        int py = p / WP, px = p - py*WP;
        int yy = py - 1;
        float va = 0.f, vs = 0.f;
        if ((unsigned)yy < HH) {
            const float* row = x + bc*HW + (size_t)yy*WW;
            int xa = px - 1, xs = px - 2;
            if ((unsigned)xa < WW) va = row[xa];
            if ((unsigned)xs < WW) vs = row[xs];
        }
        g_pxe[idx] = __float2half(va);
        g_pxo[idx] = __float2half(vs);
    }
}

// ---------------- convert static weights (permuted k: knew=(r*3+dx)*128+ic) ---
__global__ void split_w_kernel(const float* __restrict__ w1,
                               const float* __restrict__ w2,
                               const float* __restrict__ w3) {
    const float* w = (blockIdx.y == 0) ? w1 : (blockIdx.y == 1) ? w2 : w3;
    int base = blockIdx.y * CC_ * KK;
    for (int e = blockIdx.x*blockDim.x + threadIdx.x; e < CC_*KK;
         e += gridDim.x*blockDim.x) {
        int o = e / KK, knew = e - o*KK;
        int rr = knew >> 7, ic = knew & 127;
        g_w[base + e] = __float2half(w[(size_t)o*KK + ic*9 + rr]);
    }
}

// ---------------- fp16 tensor-core implicit-GEMM 3x3 conv ---------------------
// CTA: M=128 o x N=96 px. K=1152 in 36 chunks of 32, (r,dx)-major.
// Single fp16 product. 3-stage cp.async pipeline.
// Modes: 0 fp32 out; 1 padded planes (2 arrays); 2 parity-packed.
#define A_STRIDE 80
#define B_STRIDE 208
#define A_BYTES (128*A_STRIDE)
#define B_BYTES (32*B_STRIDE)
#define STG (A_BYTES + B_BYTES)       // 16896
#define SMEM_CONV (3*STG)             // 50688

__global__ __launch_bounds__(256, 2) void conv_mma_kernel(
    const __half* __restrict__ pe, const __half* __restrict__ po,
    const __half* __restrict__ w_g, long wbstride,
    void* __restrict__ p0, void* __restrict__ p1, int mode)
{
    extern __shared__ __align__(16) unsigned char smem[];
    const int b  = blockIdx.z;
    const int y  = blockIdx.y;
    const int x0 = blockIdx.x * 96;
    const int tid = threadIdx.x;
    const int lane = tid & 31, wid = tid >> 5;
    const int wm = wid & 3, wn = wid >> 2;
    const uint32_t sb = smem_u32(smem);

    const __half* peb = pe + (size_t)b*PCHW;
    const __half* pob = po + (size_t)b*PCHW;
    const __half* wg = w_g + (size_t)b*wbstride;

    int bsrc[6], bdst[6];
#pragma unroll
    for (int i = 0; i < 6; i++) {
        int slot = tid + i*256;              // < 1536
        int rowt = slot / 48, np = slot - rowt*48;
        bsrc[i] = rowt*PLANE + np*2;
        bdst[i] = rowt*B_STRIDE + np*4;
    }
    int adst[2], aoff[2];
#pragma unroll
    for (int i = 0; i < 2; i++) {
        int slot = tid + i*256;              // < 512
        int o = slot >> 2, qq = slot & 3;
        adst[i] = o*A_STRIDE + qq*16;
        aoff[i] = o*KK + qq*8;
    }

    float acc[2][6][4];
#pragma unroll
    for (int mh = 0; mh < 2; mh++)
#pragma unroll
        for (int j = 0; j < 6; j++)
#pragma unroll
            for (int t = 0; t < 4; t++) acc[mh][j][t] = 0.f;

    auto loadAB = [&](int c) {
        const uint32_t stg = sb + (c % 3)*STG;
        const int kofs = c*32;
#pragma unroll
        for (int i = 0; i < 2; i++) cp16(stg + adst[i], wg + aoff[i] + kofs);
        int r = c / 12, t = c - r*12;
        int dx = t >> 2, q = t & 3;
        int ibase = q*32*PLANE + (y + r)*WP + x0 + dx + (dx == 1);
        const __half* hp = ((dx == 1) ? pob : peb) + ibase;
        const uint32_t bb = stg + A_BYTES;
#pragma unroll
        for (int i = 0; i < 6; i++)
            cp4(bb + bdst[i], hp + bsrc[i]);
        cp_commit();
    };

    loadAB(0);
    loadAB(1);

    for (int c = 0; c < 36; c++) {
        if (c < 34) cp_wait1(); else cp_wait0();
        __syncthreads();
        if (c < 34) loadAB(c + 2);

        const uint32_t stg = sb + (c % 3)*STG;
        const uint32_t A_s = stg;
        const uint32_t B_s = stg + A_BYTES;
#pragma unroll
        for (int st = 0; st < 2; st++) {
            unsigned Af[2][4], Bf[3][4];
#pragma unroll
            for (int mh = 0; mh < 2; mh++) {
                uint32_t off = (uint32_t)(wm*32 + mh*16 + (lane & 15))*A_STRIDE
                             + ((lane >> 4) << 4) + st*32;
                ldsm4(Af[mh], A_s + off);
            }
#pragma unroll
            for (int nf = 0; nf < 3; nf++) {
                uint32_t off = (uint32_t)(st*16 + (lane & 15))*B_STRIDE
                             + wn*96 + nf*32 + ((lane >> 4) << 4);
                ldsm4t(Bf[nf], B_s + off);
            }
#pragma unroll
            for (int mh = 0; mh < 2; mh++)
#pragma unroll
                for (int j = 0; j < 6; j++)
                    mma_f16(acc[mh][j], Af[mh], &Bf[j >> 1][(j & 1)*2]);
        }
    }

    // ---- epilogue ----
    if (mode == 0) {
        float* out = (float*)p0;
#pragma unroll
        for (int mh = 0; mh < 2; mh++) {
            int o = wm*32 + mh*16 + (lane >> 2);
#pragma unroll
            for (int j = 0; j < 6; j++) {
                int x = x0 + wn*48 + j*8 + (lane & 3)*2;
                size_t i0 = ((size_t)b*CC_ + o)*HW + (size_t)y*WW + x;
                size_t i1 = i0 + (size_t)8*HW;
                *(float2*)(out + i0) = make_float2(acc[mh][j][0], acc[mh][j][1]);
                *(float2*)(out + i1) = make_float2(acc[mh][j][2], acc[mh][j][3]);
            }
        }
    } else if (mode == 1) {
        // stage plane, stride 100 per ch, +1 element shift
        __syncthreads();
        __half* sh = (__half*)smem;      // 128*100
#pragma unroll
        for (int mh = 0; mh < 2; mh++) {
            int o = wm*32 + mh*16 + (lane >> 2);
#pragma unroll
            for (int j = 0; j < 6; j++) {
                int xb = wn*48 + j*8 + (lane & 3)*2;
#pragma unroll
                for (int t = 0; t < 4; t++) {
                    int oo = o + (t >> 1)*8;
                    int xx = xb + (t & 1);
                    sh[oo*100 + xx + 1] = __float2half(acc[mh][j][t]);
                }
            }
        }
        __syncthreads();
        __half* eh = (__half*)p0;   // pae
        __half* oh = (__half*)p1;   // pao
        for (int run = wid; run < 256; run += 8) {
            int a = run >> 7, ch = run & 127;
            const __half* sp = sh + ch*100;
            __half* base = (a == 0) ? eh : oh;
            __half* dst = base + ((size_t)b*CC_ + ch)*PLANE
                        + (size_t)(y + 1)*WP + x0 + 1 + a;
            if (a == 0) {
                if (lane == 0) dst[0]  = sp[1];
                if (lane == 1) dst[95] = sp[96];
                for (int j2 = lane; j2 < 47; j2 += 32) {
                    uint32_t v = *(const uint32_t*)(sp + 2 + 2*j2);
                    *(uint32_t*)(dst + 1 + 2*j2) = v;
                }
            } else {
                for (int j2 = lane; j2 < 48; j2 += 32) {
                    uint32_t lo2 = (uint32_t)*(const unsigned short*)(sp + 1 + 2*j2);
                    uint32_t hi2 = (uint32_t)*(const unsigned short*)(sp + 2 + 2*j2);
                    *(uint32_t*)(dst + 2*j2) = lo2 | (hi2 << 16);
                }
            }
        }
    } else {
        // parity-packed: stage [ch][cx*32+qx] plane, then uint4 stores
        __syncthreads();
        __half* sh = (__half*)smem;      // 128*96
#pragma unroll
        for (int mh = 0; mh < 2; mh++) {
            int o = wm*32 + mh*16 + (lane >> 2);
#pragma unroll
            for (int j = 0; j < 6; j++) {
                int xb = wn*48 + j*8 + (lane & 3)*2;
#pragma unroll
                for (int t = 0; t < 4; t++) {
                    int oo = o + (t >> 1)*8;
                    int xx = xb + (t & 1);
                    int qx = xx / 3;
                    int cx = xx - qx*3;
                    sh[oo*96 + cx*32 + qx] = __float2half(acc[mh][j][t]);
                }
            }
        }
        __syncthreads();
        __half* ph = (__half*)p0;
        int cy = y % 3, qy = y / 3;
        int bx32 = blockIdx.x * 32;
#pragma unroll
        for (int i = 0; i < 6; i++) {
            int s = tid + i*256;      // < 1536
            int seg = s >> 2, q = s & 3;
            int ch = seg / 3, cx = seg - ch*3;
            const uint4* src = (const uint4*)(sh + ch*96 + cx*32 + q*8);
            __half* dst = ph
                + (((size_t)b*CC_ + ch)*9 + cy*3 + cx)*4096 + qy*64 + bx32 + q*8;
            *(uint4*)dst = *src;
        }
    }
}

// ---------------- tensor-core attention correlation GEMM ----------------------
// Single fp16 product. M=128(o) x N=128(i), K slab 1024.
#define AT_STRIDE 80
#define AT_BYTES (128*AT_STRIDE)   // 10240
#define AT_STG (2*AT_BYTES)        // 20480
#define SMEM_ATTN (2*AT_STG)       // 40960

__global__ __launch_bounds__(256, 2) void attn_mma_kernel(
    const __half* __restrict__ a1p, const __half* __restrict__ a2p)
{
    extern __shared__ __align__(16) unsigned char smem[];
    const int ks  = blockIdx.x;
    const int cls = blockIdx.y;
    const int b   = blockIdx.z;
    const int tid = threadIdx.x;
    const int lane = tid & 31, wid = tid >> 5;
    const int wm = wid & 3, wn = wid >> 2;
    const uint32_t sb = smem_u32(smem);

    const size_t cbase = ((size_t)b*CC_*9 + cls)*4096 + ks*1024;
    const __half* A_g = a2p + cbase;
    const __half* B_g = a1p + cbase;

    int sdst[2];
    size_t ssrc[2];
#pragma unroll
    for (int i = 0; i < 2; i++) {
        int slot = tid + i*256;            // < 512
        int r = slot >> 2, q = slot & 3;
        sdst[i] = r*AT_STRIDE + q*16;
        ssrc[i] = (size_t)r*36864 + q*8;
    }

    float acc[2][8][4];
#pragma unroll
    for (int mh = 0; mh < 2; mh++)
#pragma unroll
        for (int nj = 0; nj < 8; nj++)
#pragma unroll
            for (int t = 0; t < 4; t++) acc[mh][nj][t] = 0.f;

    auto loadAB = [&](int c) {
        const uint32_t stg = sb + (c & 1)*AT_STG;
        const int kofs = c*32;
#pragma unroll
        for (int i = 0; i < 2; i++) {
            cp16(stg + sdst[i],            A_g + ssrc[i] + kofs);
            cp16(stg + AT_BYTES + sdst[i], B_g + ssrc[i] + kofs);
        }
        cp_commit();
    };

    loadAB(0);
    for (int c = 0; c < 32; c++) {
        cp_wait0();
        __syncthreads();
        if (c < 31) loadAB(c + 1);

        const uint32_t stg = sb + (c & 1)*AT_STG;
        const uint32_t A_s = stg;
        const uint32_t B_s = stg + AT_BYTES;
#pragma unroll
        for (int st = 0; st < 2; st++) {
            unsigned Af[2][4], Bf[4][4];
#pragma unroll
            for (int mh = 0; mh < 2; mh++) {
                uint32_t off = (uint32_t)(wm*32 + mh*16 + (lane & 15))*AT_STRIDE
                             + ((lane >> 4) << 4) + st*32;
                ldsm4(Af[mh], A_s + off);
            }
#pragma unroll
            for (int ng = 0; ng < 4; ng++) {
                uint32_t off = (uint32_t)(wn*64 + ng*16 + (lane & 7)
                             + ((lane >> 3) & 1)*8)*AT_STRIDE
                             + st*32 + ((lane >> 4) & 1)*16;
                ldsm4(Bf[ng], B_s + off);
            }
#pragma unroll
            for (int mh = 0; mh < 2; mh++)
#pragma unroll
                for (int ng = 0; ng < 4; ng++)
#pragma unroll
                    for (int s2 = 0; s2 < 2; s2++)
                        mma_f16_2(acc[mh][ng*2 + s2], Af[mh],
                                  Bf[ng][s2], Bf[ng][s2 + 2]);
        }
    }

#pragma unroll
    for (int mh = 0; mh < 2; mh++) {
        int o0 = wm*32 + mh*16 + (lane >> 2);
#pragma unroll
        for (int nj = 0; nj < 8; nj++) {
            int n0 = wn*64 + nj*8 + (lane & 3)*2;
            size_t r0 = ((size_t)b*CC_ + o0)*KK;
            size_t r1 = ((size_t)b*CC_ + o0 + 8)*KK;
            atomicAdd(&g_attn[r0 + (size_t)n0*9 + cls],       acc[mh][nj][0]);
            atomicAdd(&g_attn[r0 + (size_t)(n0 + 1)*9 + cls], acc[mh][nj][1]);
            atomicAdd(&g_attn[r1 + (size_t)n0*9 + cls],       acc[mh][nj][2]);
            atomicAdd(&g_attn[r1 + (size_t)(n0 + 1)*9 + cls], acc[mh][nj][3]);
        }
    }
}

// ---------------- softmax; emits dynamic kernels as fp16, permuted k ----------
__global__ __launch_bounds__(256) void softmax_kernel() {
    __shared__ float red[256];
    const int row = blockIdx.x;
    const float* rp = g_attn + (size_t)row*KK;
    const float scale = 0.029462782549439483f;
    const int tid = threadIdx.x;

    float m = -1e30f;
    for (int e = tid; e < KK; e += 256) m = fmaxf(m, rp[e]);
    red[tid] = m; __syncthreads();
    for (int s = 128; s > 0; s >>= 1) {
        if (tid < s) red[tid] = fmaxf(red[tid], red[tid + s]);
        __syncthreads();
    }
    m = red[0] * scale;
    __syncthreads();

    float sum = 0.f;
    for (int e = tid; e < KK; e += 256) sum += expf(rp[e]*scale - m);
    red[tid] = sum; __syncthreads();
    for (int s = 128; s > 0; s >>= 1) {
        if (tid < s) red[tid] += red[tid + s];
        __syncthreads();
    }
    float inv = 1.f / red[0];

    for (int e = tid; e < KK; e += 256) {
        float p = expf(rp[e]*scale - m) * inv;
        int i = e / 9, rr = e - i*9;
        int knew = rr*128 + i;
        g_k[(size_t)row*KK + knew] = __float2half(p);
    }
}

// ---------------- BN stats over av partitioned by (group, parity) ------------
__global__ __launch_bounds__(256) void stats_kernel() {
    const int g = blockIdx.x;
    const int b = blockIdx.y;
    const int tid = threadIdx.x;
    float s00=0,s01=0,s10=0,s11=0,q00=0,q01=0,q10=0,q11=0;
    for (int c = 0; c < 4; c++) {
        const float* p = g_av + ((size_t)b*CC_ + g*4 + c)*HW;
        for (int e = tid; e < HW/2; e += 256) {
            int y = e / 96;
            int x2 = (e - y*96) * 2;
            float v0 = p[y*WW + x2];
            float v1 = p[y*WW + x2 + 1];
            if (y & 1) { s10 += v0; q10 += v0*v0; s11 += v1; q11 += v1*v1; }
            else       { s00 += v0; q00 += v0*v0; s01 += v1; q01 += v1*v1; }
        }
    }
    __shared__ float red[256];
    float vals[8] = {s00, s01, s10, s11, q00, q01, q10, q11};
#pragma unroll
    for (int v = 0; v < 8; v++) {
        red[tid] = vals[v]; __syncthreads();
        for (int st = 128; st > 0; st >>= 1) {
            if (tid < st) red[tid] += red[tid + st];
            __syncthreads();
        }
        if (tid == 0) {
            int p2 = v & 3;
            if (v < 4) atomicAdd(&g_sum[g*4 + p2],   red[0]);
            else       atomicAdd(&g_sumsq[g*4 + p2], red[0]);
        }
        __syncthreads();
    }
}

__global__ void finalize_kernel() {
    int c = threadIdx.x;
    if (c < CC_) {
        float n = (float)STAT_N;
        float mean = g_sum[c] / n;
        float var  = g_sumsq[c] / n - mean*mean;
        g_mean[c] = mean;
        g_inv[c]  = NORM_SCALE * rsqrtf(var + EPSV);
    }
}

// ---------------- fused stack-gather + BN + residual epilogue ----------------
__global__ __launch_bounds__(256) void output_kernel(const float* __restrict__ x,
                                                     const float* __restrict__ mom_p,
                                                     float* __restrict__ out) {
    const float mom = *mom_p;
    for (size_t idx = (size_t)blockIdx.x*blockDim.x + threadIdx.x; idx < (size_t)TOT;
         idx += (size_t)gridDim.x*blockDim.x) {
        size_t b = idx / CHW;
        int r  = (int)(idx - b*CHW);
        int c2 = r / HW;
        int rr = r - c2*HW;
        int Y = rr / WW, X = rr - Y*WW;
        int i2 = (Y >= 96), j2 = (X >= 96);
        int ph = Y - i2*96, pw = X - j2*96;
        int sc = (c2 & ~3) | (i2*2 + j2);
        int sy = ph*2 + ((c2 >> 1) & 1);
        int sx = pw*2 + (c2 & 1);
        float v = g_av[((size_t)b*CC_ + sc)*HW + (size_t)sy*WW + sx];
        out[idx] = mom * x[idx] + (v - g_mean[c2]) * g_inv[c2];
    }
}

// ---------------- launch -----------------------------------------------------
extern "C" void kernel_launch(void* const* d_in, const int* in_sizes, int n_in,
                              void* d_out, int out_size) {
    const float* x   = (const float*)d_in[0];
    const float* w1  = (const float*)d_in[1];
    const float* w2  = (const float*)d_in[2];
    const float* w3  = (const float*)d_in[3];
    const float* mom = (const float*)d_in[4];
    float* out = (float*)d_out;

    cudaFuncSetAttribute(conv_mma_kernel,
                         cudaFuncAttributeMaxDynamicSharedMemorySize, SMEM_CONV);
    cudaFuncSetAttribute(attn_mma_kernel,
                         cudaFuncAttributeMaxDynamicSharedMemorySize, SMEM_ATTN);

    __half *pxe, *pxo, *pae, *pao, *a1p, *a2p, *w, *k;
    float *av;
    cudaGetSymbolAddress((void**)&pxe, g_pxe);
    cudaGetSymbolAddress((void**)&pxo, g_pxo);
    cudaGetSymbolAddress((void**)&pae, g_pae);
    cudaGetSymbolAddress((void**)&pao, g_pao);
    cudaGetSymbolAddress((void**)&a1p, g_a1p);
    cudaGetSymbolAddress((void**)&a2p, g_a2p);
    cudaGetSymbolAddress((void**)&av,  g_av);
    cudaGetSymbolAddress((void**)&w,   g_w);
    cudaGetSymbolAddress((void**)&k,   g_k);

    zero_kernel<<<2048, 256>>>();
    split_x_pad_kernel<<<8192, 256>>>(x);
    split_w_kernel<<<dim3(144, 3), 256>>>(w1, w2, w3);

    dim3 cgrid(2, HH, BB);
    conv_mma_kernel<<<cgrid, 256, SMEM_CONV>>>(pxe, pxo,
        w + 0*(size_t)CC_*KK, 0, a1p, nullptr, 2);
    conv_mma_kernel<<<cgrid, 256, SMEM_CONV>>>(pxe, pxo,
        w + 1*(size_t)CC_*KK, 0, a2p, nullptr, 2);
    conv_mma_kernel<<<cgrid, 256, SMEM_CONV>>>(pxe, pxo,
        w + 2*(size_t)CC_*KK, 0, pae, pao, 1);

    attn_mma_kernel<<<dim3(4, 9, BB), 256, SMEM_ATTN>>>(a1p, a2p);
    softmax_kernel<<<BB*CC_, 256>>>();

    conv_mma_kernel<<<cgrid, 256, SMEM_CONV>>>(pae, pao,
        k, (long)CC_*KK, av, nullptr, 0);

    stats_kernel<<<dim3(32, 8), 256>>>();
    finalize_kernel<<<1, 128>>>();
    output_kernel<<<8192, 256>>>(x, mom, out);
}